// round 13
// baseline (speedup 1.0000x reference)
#include <cuda_runtime.h>
#include <cuda_fp16.h>
#include <math.h>
#include <stdint.h>

constexpr int N_TOK = 16384;
constexpr int DIM   = 2048;
constexpr int NEXP  = 64;
constexpr int TOPK  = 8;
constexpr int KCH   = 32;          // K per stage
constexpr int NS    = DIM / KCH;   // 64 stages

// scales: X,H pre-scaled by 16; W1,W2 by 64; product scale 1024
constexpr float SCL_A  = 16.0f;
constexpr float SCL_B  = 64.0f;
constexpr float INV_SC = 1.0f / 1024.0f;

// ---------------- device scratch ----------------
__device__ __half g_Xs0[(size_t)N_TOK * DIM];
__device__ __half g_Xs1[(size_t)N_TOK * DIM];
__device__ __half g_Hs0[(size_t)N_TOK * DIM];
__device__ __half g_Hs1[(size_t)N_TOK * DIM];
__device__ __half g_W1T0[(size_t)DIM * DIM];   // [n][k]
__device__ __half g_W1T1[(size_t)DIM * DIM];
__device__ __half g_W2T0[(size_t)NEXP * DIM];  // [e][k]
__device__ __half g_W2T1[(size_t)NEXP * DIM];
__device__ float g_probsum[NEXP];
__device__ int   g_cnt[NEXP];
__device__ int   g_done;

// ---------------- helpers ----------------
__device__ __forceinline__ float gelu_exact(float x) {
    return 0.5f * x * (1.0f + erff(x * 0.70710678118654752f));
}
__device__ __forceinline__ uint32_t smem_u32(const void* p) {
    uint32_t a;
    asm("{ .reg .u64 t; cvta.to.shared.u64 t, %1; cvt.u32.u64 %0, t; }" : "=r"(a) : "l"(p));
    return a;
}
__device__ __forceinline__ void cpa16(uint32_t dst, const void* src) {
    asm volatile("cp.async.cg.shared.global [%0], [%1], 16;" :: "r"(dst), "l"(src) : "memory");
}
__device__ __forceinline__ void cp_commit() {
    asm volatile("cp.async.commit_group;" ::: "memory");
}
__device__ __forceinline__ void cp_wait1() {
    asm volatile("cp.async.wait_group 1;" ::: "memory");
}
__device__ __forceinline__ void ldsm4(uint32_t* r, uint32_t a) {
    asm volatile("ldmatrix.sync.aligned.m8n8.x4.shared.b16 {%0,%1,%2,%3}, [%4];"
                 : "=r"(r[0]), "=r"(r[1]), "=r"(r[2]), "=r"(r[3]) : "r"(a));
}
__device__ __forceinline__ void mma16816(float* c, const uint32_t* a, const uint32_t* b) {
    asm volatile("mma.sync.aligned.m16n8k16.row.col.f32.f16.f16.f32 "
                 "{%0,%1,%2,%3}, {%4,%5,%6,%7}, {%8,%9}, {%0,%1,%2,%3};"
                 : "+f"(c[0]), "+f"(c[1]), "+f"(c[2]), "+f"(c[3])
                 : "r"(a[0]), "r"(a[1]), "r"(a[2]), "r"(a[3]), "r"(b[0]), "r"(b[1]));
}
__device__ __forceinline__ void split2(float v, __half& h0, __half& h1) {
    h0 = __float2half_rn(v);
    h1 = __float2half_rn(v - __half2float(h0));
}

// ---------------- fused preprocessing ----------------
// blocks [0,4096): split X; [4096,8192): transpose+split W1; [8192,8320): W2.
// block 8192 also zeroes the loss accumulators + completion counter.
__global__ __launch_bounds__(256) void k_prep(const float* __restrict__ x,
                                              const float* __restrict__ W1,
                                              const float* __restrict__ W2) {
    __shared__ float t[32][33];
    const int b = blockIdx.x;
    const int tid = threadIdx.x;

    if (b < 4096) {
        const size_t total = (size_t)N_TOK * DIM / 4;
        for (size_t i = (size_t)b * 256 + tid; i < total; i += (size_t)4096 * 256) {
            float4 v = ((const float4*)x)[i];
            __half a0, a1, b0, b1, c0, c1, d0, d1;
            split2(SCL_A * v.x, a0, a1); split2(SCL_A * v.y, b0, b1);
            split2(SCL_A * v.z, c0, c1); split2(SCL_A * v.w, d0, d1);
            __half2 p0a = __halves2half2(a0, b0), p0b = __halves2half2(c0, d0);
            __half2 p1a = __halves2half2(a1, b1), p1b = __halves2half2(c1, d1);
            ((uint2*)g_Xs0)[i] = make_uint2(*(uint32_t*)&p0a, *(uint32_t*)&p0b);
            ((uint2*)g_Xs1)[i] = make_uint2(*(uint32_t*)&p1a, *(uint32_t*)&p1b);
        }
        return;
    }

    const float* src;
    __half *d0, *d1;
    int R, C, bx, by;
    if (b < 8192) {
        const int idx = b - 4096;
        src = W1; d0 = g_W1T0; d1 = g_W1T1; R = DIM; C = DIM;
        bx = (idx & 63) * 32; by = (idx >> 6) * 32;
    } else {
        if (b == 8192) {
            if (tid < NEXP) { g_probsum[tid] = 0.0f; g_cnt[tid] = 0; }
            if (tid == NEXP) g_done = 0;
        }
        const int idx = b - 8192;
        src = W2; d0 = g_W2T0; d1 = g_W2T1; R = DIM; C = NEXP;
        bx = (idx & 1) * 32; by = (idx >> 1) * 32;
    }
    const int tx = tid & 31, ty = tid >> 5;   // 32 x 8
#pragma unroll
    for (int i = 0; i < 32; i += 8)
        t[ty + i][tx] = src[(size_t)(by + ty + i) * C + bx + tx];
    __syncthreads();
#pragma unroll
    for (int i = 0; i < 32; i += 8) {
        float v = SCL_B * t[tx][ty + i];
        __half s0, s1; split2(v, s0, s1);
        size_t o = (size_t)(bx + ty + i) * R + by + tx;
        d0[o] = s0; d1[o] = s1;
    }
}

// ---------------- GEMM1: H = gelu(X@W1+b1), 128x128 tile, 3-stage ring ----------------
// C = A0*B0 + A0*B1 + A1*B0 (fp16 2-split, fp32 accum).
// 64B rows, chunk swizzle (c ^ ((r>>1)&3)).
// R9/R11 inner loop: 14 ldsm/kstep, 16-mma runs, prefetch after first hh block.
// Epilogue stages H splits through smem (row stride 272 B, 16B-aligned).
__global__ __launch_bounds__(256, 2)
void k_mma1(const float* __restrict__ bias) {
    constexpr int SA_B = 128 * 64;           // 8192 per split per stage
    constexpr int SB_B = 128 * 64;
    constexpr int STGB = 2 * SA_B + 2 * SB_B;

    extern __shared__ char sm[];
    const int tid = threadIdx.x, wid = tid >> 5, lane = tid & 31;
    const int warp_m = wid >> 2, warp_n = wid & 3;
    const int bm = blockIdx.y * 128;
    const int bn = blockIdx.x * 128;
    const uint32_t smb = smem_u32(sm);

    const int lr = lane & 7, lg = lane >> 3;
    const int a_row = lr + (lg & 1) * 8;
    const int a_chb = lg >> 1;
    const int a_swz = (a_row >> 1) & 3;
    const int b_row = lr + (lg >> 1) * 8;
    const int b_chb = lg & 1;
    const int b_swz = (b_row >> 1) & 3;

    float acc[4][4][4];
#pragma unroll
    for (int i = 0; i < 4; ++i)
#pragma unroll
        for (int j = 0; j < 4; ++j)
#pragma unroll
            for (int e = 0; e < 4; ++e) acc[i][j][e] = 0.0f;

    auto load_stage = [&](int s, int buf) {
        const int k0 = s * KCH;
        const uint32_t base = smb + (uint32_t)(buf * STGB);
#pragma unroll
        for (int t = tid; t < 2048; t += 256) {
            if (t < 1024) {
                int sp = t >> 9, idx = t & 511;
                int r = idx >> 2, c = idx & 3;
                const __half* src = (sp == 0 ? g_Xs0 : g_Xs1) + (size_t)(bm + r) * DIM + k0 + c * 8;
                cpa16(base + (uint32_t)(sp * SA_B + r * 64 + ((c ^ ((r >> 1) & 3)) << 4)), src);
            } else {
                int u = t - 1024;
                int sp = u >> 9, idx = u & 511;
                int r = idx >> 2, c = idx & 3;
                const __half* src = (sp == 0 ? g_W1T0 : g_W1T1) + (size_t)(bn + r) * DIM + k0 + c * 8;
                cpa16(base + (uint32_t)(2 * SA_B + sp * SB_B + r * 64 + ((c ^ ((r >> 1) & 3)) << 4)), src);
            }
        }
        cp_commit();
    };

    auto stage_body = [&](int s, int rb, int wb) {
        cp_wait1();
        __syncthreads();

        const uint32_t base = smb + (uint32_t)(rb * STGB);
        const uint32_t aB = base + (uint32_t)((warp_m * 64 + a_row) * 64);
        const uint32_t bB = base + 2 * SA_B + (uint32_t)((warp_n * 32 + b_row) * 64);

        uint32_t af[4][4], bf[2][4];
        // ---- ks = 0 ----
        {
            const uint32_t ac = (uint32_t)((a_chb ^ a_swz) << 4);
            const uint32_t bc = (uint32_t)((b_chb ^ b_swz) << 4);
#pragma unroll
            for (int np = 0; np < 2; ++np)
                ldsm4(bf[np], bB + (uint32_t)(np * 1024) + bc);
#pragma unroll
            for (int mt = 0; mt < 4; ++mt)
                ldsm4(af[mt], aB + (uint32_t)(mt * 1024) + ac);
#pragma unroll
            for (int mt = 0; mt < 4; ++mt)
#pragma unroll
                for (int nt = 0; nt < 4; ++nt)
                    mma16816(acc[mt][nt], af[mt], &bf[nt >> 1][(nt & 1) * 2]);

            // prefetch now — tensor pipe has 64 mmas in flight
            if (s + 2 < NS) load_stage(s + 2, wb);
            else cp_commit();

            // hl: B1, A0 resident
#pragma unroll
            for (int np = 0; np < 2; ++np)
                ldsm4(bf[np], bB + (uint32_t)(SB_B + np * 1024) + bc);
#pragma unroll
            for (int mt = 0; mt < 4; ++mt)
#pragma unroll
                for (int nt = 0; nt < 4; ++nt)
                    mma16816(acc[mt][nt], af[mt], &bf[nt >> 1][(nt & 1) * 2]);
            // lh: A1, reload B0
#pragma unroll
            for (int mt = 0; mt < 4; ++mt)
                ldsm4(af[mt], aB + (uint32_t)(SA_B + mt * 1024) + ac);
#pragma unroll
            for (int np = 0; np < 2; ++np)
                ldsm4(bf[np], bB + (uint32_t)(np * 1024) + bc);
#pragma unroll
            for (int mt = 0; mt < 4; ++mt)
#pragma unroll
                for (int nt = 0; nt < 4; ++nt)
                    mma16816(acc[mt][nt], af[mt], &bf[nt >> 1][(nt & 1) * 2]);
        }
        // ---- ks = 1 ----
        {
            const uint32_t ac = (uint32_t)(((a_chb + 2) ^ a_swz) << 4);
            const uint32_t bc = (uint32_t)(((b_chb + 2) ^ b_swz) << 4);
#pragma unroll
            for (int np = 0; np < 2; ++np)
                ldsm4(bf[np], bB + (uint32_t)(np * 1024) + bc);
#pragma unroll
            for (int mt = 0; mt < 4; ++mt)
                ldsm4(af[mt], aB + (uint32_t)(mt * 1024) + ac);
#pragma unroll
            for (int mt = 0; mt < 4; ++mt)
#pragma unroll
                for (int nt = 0; nt < 4; ++nt)
                    mma16816(acc[mt][nt], af[mt], &bf[nt >> 1][(nt & 1) * 2]);
#pragma unroll
            for (int np = 0; np < 2; ++np)
                ldsm4(bf[np], bB + (uint32_t)(SB_B + np * 1024) + bc);
#pragma unroll
            for (int mt = 0; mt < 4; ++mt)
#pragma unroll
                for (int nt = 0; nt < 4; ++nt)
                    mma16816(acc[mt][nt], af[mt], &bf[nt >> 1][(nt & 1) * 2]);
#pragma unroll
            for (int mt = 0; mt < 4; ++mt)
                ldsm4(af[mt], aB + (uint32_t)(SA_B + mt * 1024) + ac);
#pragma unroll
            for (int np = 0; np < 2; ++np)
                ldsm4(bf[np], bB + (uint32_t)(np * 1024) + bc);
#pragma unroll
            for (int mt = 0; mt < 4; ++mt)
#pragma unroll
                for (int nt = 0; nt < 4; ++nt)
                    mma16816(acc[mt][nt], af[mt], &bf[nt >> 1][(nt & 1) * 2]);
        }
    };

    load_stage(0, 0);
    load_stage(1, 1);

    static_assert(NS == 3 * 21 + 1, "stage unroll assumes NS==64");
#pragma unroll 1
    for (int i = 0; i < 21; ++i) {
        const int s = i * 3;
        stage_body(s + 0, 0, 2);
        stage_body(s + 1, 1, 0);
        stage_body(s + 2, 2, 1);
    }
    stage_body(NS - 1, 0, 2);

    // ---- epilogue: bias + gelu + fp16 re-split, staged via smem ----
    __syncthreads();   // ring buffers are dead; reuse as staging
    constexpr int RW = 136;                     // row stride in halves (272 B, 16B-aligned)
    __half* h0 = (__half*)sm;                   // 128 x 136 halves = 34816 B
    __half* h1 = (__half*)(sm + 128 * RW * 2);  // second split (total 69632 <= 98304)
#pragma unroll
    for (int mt = 0; mt < 4; ++mt) {
        const int rl0 = warp_m * 64 + mt * 16 + (lane >> 2);
        const int rl1 = rl0 + 8;
#pragma unroll
        for (int nt = 0; nt < 4; ++nt) {
            const int cl = warp_n * 32 + nt * 8 + ((lane & 3) << 1);
            const int cg = bn + cl;
            const float bv0 = __ldg(bias + cg), bv1 = __ldg(bias + cg + 1);
            float v00 = SCL_A * gelu_exact(acc[mt][nt][0] * INV_SC + bv0);
            float v01 = SCL_A * gelu_exact(acc[mt][nt][1] * INV_SC + bv1);
            float v10 = SCL_A * gelu_exact(acc[mt][nt][2] * INV_SC + bv0);
            float v11 = SCL_A * gelu_exact(acc[mt][nt][3] * INV_SC + bv1);
            __half h00a, h00b, h01a, h01b, h10a, h10b, h11a, h11b;
            split2(v00, h00a, h00b); split2(v01, h01a, h01b);
            split2(v10, h10a, h10b); split2(v11, h11a, h11b);
            *(__half2*)(h0 + rl0 * RW + cl) = __halves2half2(h00a, h01a);
            *(__half2*)(h1 + rl0 * RW + cl) = __halves2half2(h00b, h01b);
            *(__half2*)(h0 + rl1 * RW + cl) = __halves2half2(h10a, h11a);
            *(__half2*)(h1 + rl1 * RW + cl) = __halves2half2(h10b, h11b);
        }
    }
    __syncthreads();
    {
        const int row = tid >> 1, ch = tid & 1;   // each thread: 64 halves = 128 B
        const __half* s0 = h0 + row * RW + ch * 64;
        const __half* s1 = h1 + row * RW + ch * 64;
        const size_t go = (size_t)(bm + row) * DIM + bn + ch * 64;
#pragma unroll
        for (int q = 0; q < 8; ++q)
            ((uint4*)(g_Hs0 + go))[q] = ((const uint4*)s0)[q];
#pragma unroll
        for (int q = 0; q < 8; ++q)
            ((uint4*)(g_Hs1 + go))[q] = ((const uint4*)s1)[q];
    }
}

// ---------------- GEMM2 + fused router + fused loss ----------------
__global__ __launch_bounds__(256, 2)
void k_gemm2r(const float* __restrict__ bias,
              float* __restrict__ out_rw, float* __restrict__ out_idx,
              float* __restrict__ out_loss, int write_idx) {
    constexpr int SA_B = 64 * 64;            // 4096 per split per stage
    constexpr int SB_B = 64 * 64;
    constexpr int STGB = 2 * SA_B + 2 * SB_B;  // 16384
    constexpr int RWL  = 66;                 // padded logits row (floats)

    extern __shared__ char sm[];
    __shared__ float psum_sh[NEXP];
    __shared__ int   cnt_sh[NEXP];
    __shared__ int   s_last;

    const int tid = threadIdx.x, wid = tid >> 5, lane = tid & 31;
    const int warp_m = wid >> 2, warp_n = wid & 3;
    const int bm = blockIdx.x * 64;
    const uint32_t smb = smem_u32(sm);

    if (tid < NEXP) { psum_sh[tid] = 0.0f; cnt_sh[tid] = 0; }

    const int lr = lane & 7, lg = lane >> 3;
    const int a_row = lr + (lg & 1) * 8;
    const int a_chb = lg >> 1;
    const int a_swz = (a_row >> 1) & 3;
    const int b_row = lr + (lg >> 1) * 8;
    const int b_chb = lg & 1;
    const int b_swz = (b_row >> 1) & 3;

    float acc[2][2][4];
#pragma unroll
    for (int i = 0; i < 2; ++i)
#pragma unroll
        for (int j = 0; j < 2; ++j)
#pragma unroll
            for (int e = 0; e < 4; ++e) acc[i][j][e] = 0.0f;

    auto load_stage = [&](int s, int buf) {
        const int k0 = s * KCH;
        const uint32_t base = smb + (uint32_t)(buf * STGB);
#pragma unroll
        for (int t = tid; t < 1024; t += 256) {
            if (t < 512) {
                int sp = t >> 8, idx = t & 255;
                int r = idx >> 2, c = idx & 3;
                const __half* src = (sp == 0 ? g_Hs0 : g_Hs1) + (size_t)(bm + r) * DIM + k0 + c * 8;
                cpa16(base + (uint32_t)(sp * SA_B + r * 64 + ((c ^ ((r >> 1) & 3)) << 4)), src);
            } else {
                int u = t - 512;
                int sp = u >> 8, idx = u & 255;
                int r = idx >> 2, c = idx & 3;
                const __half* src = (sp == 0 ? g_W2T0 : g_W2T1) + (size_t)r * DIM + k0 + c * 8;
                cpa16(base + (uint32_t)(2 * SA_B + sp * SB_B + r * 64 + ((c ^ ((r >> 1) & 3)) << 4)), src);
            }
        }
        cp_commit();
    };

    load_stage(0, 0);
    load_stage(1, 1);

    int rbuf = 0, wbuf = 2;
#pragma unroll 1
    for (int s = 0; s < NS; ++s) {
        cp_wait1();
        __syncthreads();

        if (s + 2 < NS) load_stage(s + 2, wbuf);
        else cp_commit();

        const uint32_t base = smb + (uint32_t)(rbuf * STGB);
        const uint32_t aB = base + (uint32_t)((warp_m * 32 + a_row) * 64);
        const uint32_t bB = base + 2 * SA_B + (uint32_t)((warp_n * 16 + b_row) * 64);

        uint32_t af[2][4], bf[4];
#pragma unroll
        for (int ks = 0; ks < 2; ++ks) {
            const uint32_t ac = (uint32_t)(((a_chb + 2 * ks) ^ a_swz) << 4);
            const uint32_t bc = (uint32_t)(((b_chb + 2 * ks) ^ b_swz) << 4);
            ldsm4(bf, bB + bc);
#pragma unroll
            for (int mt = 0; mt < 2; ++mt)
                ldsm4(af[mt], aB + (uint32_t)(mt * 1024) + ac);
#pragma unroll
            for (int mt = 0; mt < 2; ++mt)
#pragma unroll
                for (int nt = 0; nt < 2; ++nt)
                    mma16816(acc[mt][nt], af[mt], &bf[nt * 2]);
            ldsm4(bf, bB + (uint32_t)SB_B + bc);
#pragma unroll
            for (int mt = 0; mt < 2; ++mt)
#pragma unroll
                for (int nt = 0; nt < 2; ++nt)
                    mma16816(acc[mt][nt], af[mt], &bf[nt * 2]);
#pragma unroll
            for (int mt = 0; mt < 2; ++mt)
                ldsm4(af[mt], aB + (uint32_t)(SA_B + mt * 1024) + ac);
            ldsm4(bf, bB + bc);
#pragma unroll
            for (int mt = 0; mt < 2; ++mt)
#pragma unroll
                for (int nt = 0; nt < 2; ++nt)
                    mma16816(acc[mt][nt], af[mt], &bf[nt * 2]);
        }

        rbuf = (rbuf == 2) ? 0 : rbuf + 1;
        wbuf = (wbuf == 2) ? 0 : wbuf + 1;
    }

    // stage logits (bias added) into smem, reusing the ring space
    __syncthreads();
    float* sl = (float*)sm;   // 64 x 66 floats
#pragma unroll
    for (int mt = 0; mt < 2; ++mt) {
        const int r0 = warp_m * 32 + mt * 16 + (lane >> 2);
        const int r1 = r0 + 8;
#pragma unroll
        for (int nt = 0; nt < 2; ++nt) {
            const int cl = warp_n * 16 + nt * 8 + ((lane & 3) << 1);
            const float bv0 = __ldg(bias + cl), bv1 = __ldg(bias + cl + 1);
            sl[r0 * RWL + cl]     = acc[mt][nt][0] * INV_SC + bv0;
            sl[r0 * RWL + cl + 1] = acc[mt][nt][1] * INV_SC + bv1;
            sl[r1 * RWL + cl]     = acc[mt][nt][2] * INV_SC + bv0;
            sl[r1 * RWL + cl + 1] = acc[mt][nt][3] * INV_SC + bv1;
        }
    }
    __syncthreads();

    // fused router: each warp handles 8 tokens
    const float NEG_INF = __int_as_float(0xff800000);
#pragma unroll 1
    for (int tk = 0; tk < 8; ++tk) {
        const int t = wid * 8 + tk;
        float v0 = sl[t * RWL + lane];
        float v1 = sl[t * RWL + 32 + lane];

        float mx = fmaxf(v0, v1);
#pragma unroll
        for (int o = 16; o; o >>= 1) mx = fmaxf(mx, __shfl_xor_sync(0xffffffffu, mx, o));
        float p0 = expf(v0 - mx), p1 = expf(v1 - mx);
        float s = p0 + p1;
#pragma unroll
        for (int o = 16; o; o >>= 1) s += __shfl_xor_sync(0xffffffffu, s, o);
        float inv = 1.0f / s;
        atomicAdd(&psum_sh[lane], p0 * inv);
        atomicAdd(&psum_sh[lane + 32], p1 * inv);

        float w0 = v0, w1 = v1;
        float topv[TOPK]; int topi[TOPK];
#pragma unroll
        for (int k = 0; k < TOPK; ++k) {
            float bv; int bi;
            if (w0 >= w1) { bv = w0; bi = lane; } else { bv = w1; bi = lane + 32; }
#pragma unroll
            for (int o = 16; o; o >>= 1) {
                float ov = __shfl_xor_sync(0xffffffffu, bv, o);
                int   oi = __shfl_xor_sync(0xffffffffu, bi, o);
                if (ov > bv || (ov == bv && oi < bi)) { bv = ov; bi = oi; }
            }
            topv[k] = bv; topi[k] = bi;
            if (bi == lane) w0 = NEG_INF;
            if (bi == lane + 32) w1 = NEG_INF;
        }
        float es[TOPK], ss = 0.0f;
#pragma unroll
        for (int k = 0; k < TOPK; ++k) { es[k] = expf(topv[k] - topv[0]); ss += es[k]; }
        float invs = 1.0f / ss;
        float r0 = 0.0f, r1 = 0.0f;
#pragma unroll
        for (int k = 0; k < TOPK; ++k) {
            float w = es[k] * invs;
            if (topi[k] == lane) r0 = w;
            if (topi[k] == lane + 32) r1 = w;
        }
        const int tg = bm + t;
        out_rw[(size_t)tg * NEXP + lane]      = r0;
        out_rw[(size_t)tg * NEXP + 32 + lane] = r1;

        if (lane == 0) {
#pragma unroll
            for (int k = 0; k < TOPK; ++k) {
                if (write_idx) out_idx[(size_t)tg * TOPK + k] = (float)topi[k];
                atomicAdd(&cnt_sh[topi[k]], 1);
            }
        }
    }

    __syncthreads();
    if (tid < NEXP) {
        atomicAdd(&g_probsum[tid], psum_sh[tid]);
        atomicAdd(&g_cnt[tid], cnt_sh[tid]);
    }

    // last CTA computes the loss
    if (out_loss) {
        __threadfence();
        if (tid == 0) {
            int done = atomicAdd(&g_done, 1);
            s_last = (done == (int)gridDim.x - 1);
        }
        __syncthreads();
        if (s_last) {
            float* terms = (float*)sm;
            const float invN = 1.0f / (float)N_TOK;
            if (tid < NEXP)
                terms[tid] = ((float)g_cnt[tid] * invN) * (g_probsum[tid] * invN);
            __syncthreads();
            if (tid == 0) {
                float a = 0.0f;
                for (int i = 0; i < NEXP; ++i) a += terms[i];
                *out_loss = (float)NEXP * a;
            }
        }
    }
}

// ---------------- host launch ----------------
extern "C" void kernel_launch(void* const* d_in, const int* in_sizes, int n_in,
                              void* d_out, int out_size) {
    const float* x  = (const float*)d_in[0];
    const float* W1 = (const float*)d_in[1];
    const float* b1 = (const float*)d_in[2];
    const float* W2 = (const float*)d_in[3];
    const float* b2 = (const float*)d_in[4];

    float* out = (float*)d_out;
    float* out_rw = out;
    float* out_idx = nullptr;
    float* out_loss = nullptr;
    const long rw_elems = (long)N_TOK * NEXP;
    const long idx_elems = (long)N_TOK * TOPK;
    int has_idx = 0;
    if ((long)out_size >= rw_elems + idx_elems) { out_idx = out + rw_elems; has_idx = 1; }
    if ((long)out_size >= rw_elems + idx_elems + 1) out_loss = out + rw_elems + idx_elems;

    constexpr int SM1 = 3 * (2 * 128 * 64 + 2 * 128 * 64);  // 98304
    constexpr int SM2 = 3 * (2 * 64 * 64 + 2 * 64 * 64);    // 49152
    cudaFuncSetAttribute(k_mma1,   cudaFuncAttributeMaxDynamicSharedMemorySize, SM1);
    cudaFuncSetAttribute(k_gemm2r, cudaFuncAttributeMaxDynamicSharedMemorySize, SM2);

    k_prep<<<8320, 256>>>(x, W1, W2);

    k_mma1<<<dim3(16, 128), 256, SM1>>>(b1);

    k_gemm2r<<<dim3(256), 256, SM2>>>(b2, out_rw, out_idx, out_loss, has_idx);
}

// round 14
// speedup vs baseline: 1.0144x; 1.0144x over previous
#include <cuda_runtime.h>
#include <cuda_fp16.h>
#include <math.h>
#include <stdint.h>

constexpr int N_TOK = 16384;
constexpr int DIM   = 2048;
constexpr int NEXP  = 64;
constexpr int TOPK  = 8;
constexpr int KCH   = 32;          // K per stage
constexpr int NS    = DIM / KCH;   // 64 stages

// scales: X,H pre-scaled by 16; W1,W2 by 64; product scale 1024
constexpr float SCL_A  = 16.0f;
constexpr float SCL_B  = 64.0f;
constexpr float INV_SC = 1.0f / 1024.0f;

// ---------------- device scratch ----------------
__device__ __half g_Xs0[(size_t)N_TOK * DIM];
__device__ __half g_Xs1[(size_t)N_TOK * DIM];
__device__ __half g_Hs0[(size_t)N_TOK * DIM];
__device__ __half g_Hs1[(size_t)N_TOK * DIM];
__device__ __half g_W1T0[(size_t)DIM * DIM];   // [n][k]
__device__ __half g_W1T1[(size_t)DIM * DIM];
__device__ __half g_W2T0[(size_t)NEXP * DIM];  // [e][k]
__device__ __half g_W2T1[(size_t)NEXP * DIM];
__device__ float g_probsum[NEXP];
__device__ int   g_cnt[NEXP];
__device__ int   g_done;

// ---------------- helpers ----------------
__device__ __forceinline__ float gelu_exact(float x) {
    return 0.5f * x * (1.0f + erff(x * 0.70710678118654752f));
}
__device__ __forceinline__ uint32_t smem_u32(const void* p) {
    uint32_t a;
    asm("{ .reg .u64 t; cvta.to.shared.u64 t, %1; cvt.u32.u64 %0, t; }" : "=r"(a) : "l"(p));
    return a;
}
__device__ __forceinline__ void cpa16(uint32_t dst, const void* src) {
    asm volatile("cp.async.cg.shared.global [%0], [%1], 16;" :: "r"(dst), "l"(src) : "memory");
}
__device__ __forceinline__ void cp_commit() {
    asm volatile("cp.async.commit_group;" ::: "memory");
}
__device__ __forceinline__ void cp_wait1() {
    asm volatile("cp.async.wait_group 1;" ::: "memory");
}
__device__ __forceinline__ void ldsm4(uint32_t* r, uint32_t a) {
    asm volatile("ldmatrix.sync.aligned.m8n8.x4.shared.b16 {%0,%1,%2,%3}, [%4];"
                 : "=r"(r[0]), "=r"(r[1]), "=r"(r[2]), "=r"(r[3]) : "r"(a));
}
__device__ __forceinline__ void mma16816(float* c, const uint32_t* a, const uint32_t* b) {
    asm volatile("mma.sync.aligned.m16n8k16.row.col.f32.f16.f16.f32 "
                 "{%0,%1,%2,%3}, {%4,%5,%6,%7}, {%8,%9}, {%0,%1,%2,%3};"
                 : "+f"(c[0]), "+f"(c[1]), "+f"(c[2]), "+f"(c[3])
                 : "r"(a[0]), "r"(a[1]), "r"(a[2]), "r"(a[3]), "r"(b[0]), "r"(b[1]));
}
__device__ __forceinline__ void split2(float v, __half& h0, __half& h1) {
    h0 = __float2half_rn(v);
    h1 = __float2half_rn(v - __half2float(h0));
}

// ---------------- fused preprocessing ----------------
// blocks [0,4096): split X; [4096,8192): transpose+split W1; [8192,8320): W2.
// block 8192 also zeroes the loss accumulators + completion counter.
__global__ __launch_bounds__(256) void k_prep(const float* __restrict__ x,
                                              const float* __restrict__ W1,
                                              const float* __restrict__ W2) {
    __shared__ float t[32][33];
    const int b = blockIdx.x;
    const int tid = threadIdx.x;

    if (b < 4096) {
        const size_t total = (size_t)N_TOK * DIM / 4;
        for (size_t i = (size_t)b * 256 + tid; i < total; i += (size_t)4096 * 256) {
            float4 v = ((const float4*)x)[i];
            __half a0, a1, b0, b1, c0, c1, d0, d1;
            split2(SCL_A * v.x, a0, a1); split2(SCL_A * v.y, b0, b1);
            split2(SCL_A * v.z, c0, c1); split2(SCL_A * v.w, d0, d1);
            __half2 p0a = __halves2half2(a0, b0), p0b = __halves2half2(c0, d0);
            __half2 p1a = __halves2half2(a1, b1), p1b = __halves2half2(c1, d1);
            ((uint2*)g_Xs0)[i] = make_uint2(*(uint32_t*)&p0a, *(uint32_t*)&p0b);
            ((uint2*)g_Xs1)[i] = make_uint2(*(uint32_t*)&p1a, *(uint32_t*)&p1b);
        }
        return;
    }

    const float* src;
    __half *d0, *d1;
    int R, C, bx, by;
    if (b < 8192) {
        const int idx = b - 4096;
        src = W1; d0 = g_W1T0; d1 = g_W1T1; R = DIM; C = DIM;
        bx = (idx & 63) * 32; by = (idx >> 6) * 32;
    } else {
        if (b == 8192) {
            if (tid < NEXP) { g_probsum[tid] = 0.0f; g_cnt[tid] = 0; }
            if (tid == NEXP) g_done = 0;
        }
        const int idx = b - 8192;
        src = W2; d0 = g_W2T0; d1 = g_W2T1; R = DIM; C = NEXP;
        bx = (idx & 1) * 32; by = (idx >> 1) * 32;
    }
    const int tx = tid & 31, ty = tid >> 5;   // 32 x 8
#pragma unroll
    for (int i = 0; i < 32; i += 8)
        t[ty + i][tx] = src[(size_t)(by + ty + i) * C + bx + tx];
    __syncthreads();
#pragma unroll
    for (int i = 0; i < 32; i += 8) {
        float v = SCL_B * t[tx][ty + i];
        __half s0, s1; split2(v, s0, s1);
        size_t o = (size_t)(bx + ty + i) * R + by + tx;
        d0[o] = s0; d1[o] = s1;
    }
}

// ---------------- GEMM1: H = gelu(X@W1+b1), 128x128 tile, 3-stage ring ----------------
// C = A0*B0 + A0*B1 + A1*B0 (fp16 2-split, fp32 accum).
// 64B rows, chunk swizzle (c ^ ((r>>1)&3)).
// R9/R11 inner loop: 14 ldsm/kstep, 16-mma runs, prefetch after first hh block.
// Direct-store epilogue (measured best, R11).
__global__ __launch_bounds__(256, 2)
void k_mma1(const float* __restrict__ bias) {
    constexpr int SA_B = 128 * 64;           // 8192 per split per stage
    constexpr int SB_B = 128 * 64;
    constexpr int STGB = 2 * SA_B + 2 * SB_B;

    extern __shared__ char sm[];
    const int tid = threadIdx.x, wid = tid >> 5, lane = tid & 31;
    const int warp_m = wid >> 2, warp_n = wid & 3;
    const int bm = blockIdx.y * 128;
    const int bn = blockIdx.x * 128;
    const uint32_t smb = smem_u32(sm);

    const int lr = lane & 7, lg = lane >> 3;
    const int a_row = lr + (lg & 1) * 8;
    const int a_chb = lg >> 1;
    const int a_swz = (a_row >> 1) & 3;
    const int b_row = lr + (lg >> 1) * 8;
    const int b_chb = lg & 1;
    const int b_swz = (b_row >> 1) & 3;

    float acc[4][4][4];
#pragma unroll
    for (int i = 0; i < 4; ++i)
#pragma unroll
        for (int j = 0; j < 4; ++j)
#pragma unroll
            for (int e = 0; e < 4; ++e) acc[i][j][e] = 0.0f;

    auto load_stage = [&](int s, int buf) {
        const int k0 = s * KCH;
        const uint32_t base = smb + (uint32_t)(buf * STGB);
#pragma unroll
        for (int t = tid; t < 2048; t += 256) {
            if (t < 1024) {
                int sp = t >> 9, idx = t & 511;
                int r = idx >> 2, c = idx & 3;
                const __half* src = (sp == 0 ? g_Xs0 : g_Xs1) + (size_t)(bm + r) * DIM + k0 + c * 8;
                cpa16(base + (uint32_t)(sp * SA_B + r * 64 + ((c ^ ((r >> 1) & 3)) << 4)), src);
            } else {
                int u = t - 1024;
                int sp = u >> 9, idx = u & 511;
                int r = idx >> 2, c = idx & 3;
                const __half* src = (sp == 0 ? g_W1T0 : g_W1T1) + (size_t)(bn + r) * DIM + k0 + c * 8;
                cpa16(base + (uint32_t)(2 * SA_B + sp * SB_B + r * 64 + ((c ^ ((r >> 1) & 3)) << 4)), src);
            }
        }
        cp_commit();
    };

    auto stage_body = [&](int s, int rb, int wb) {
        cp_wait1();
        __syncthreads();

        const uint32_t base = smb + (uint32_t)(rb * STGB);
        const uint32_t aB = base + (uint32_t)((warp_m * 64 + a_row) * 64);
        const uint32_t bB = base + 2 * SA_B + (uint32_t)((warp_n * 32 + b_row) * 64);

        uint32_t af[4][4], bf[2][4];
        // ---- ks = 0 ----
        {
            const uint32_t ac = (uint32_t)((a_chb ^ a_swz) << 4);
            const uint32_t bc = (uint32_t)((b_chb ^ b_swz) << 4);
#pragma unroll
            for (int np = 0; np < 2; ++np)
                ldsm4(bf[np], bB + (uint32_t)(np * 1024) + bc);
#pragma unroll
            for (int mt = 0; mt < 4; ++mt)
                ldsm4(af[mt], aB + (uint32_t)(mt * 1024) + ac);
#pragma unroll
            for (int mt = 0; mt < 4; ++mt)
#pragma unroll
                for (int nt = 0; nt < 4; ++nt)
                    mma16816(acc[mt][nt], af[mt], &bf[nt >> 1][(nt & 1) * 2]);

            // prefetch now — tensor pipe has 64 mmas in flight
            if (s + 2 < NS) load_stage(s + 2, wb);
            else cp_commit();

            // hl: B1, A0 resident
#pragma unroll
            for (int np = 0; np < 2; ++np)
                ldsm4(bf[np], bB + (uint32_t)(SB_B + np * 1024) + bc);
#pragma unroll
            for (int mt = 0; mt < 4; ++mt)
#pragma unroll
                for (int nt = 0; nt < 4; ++nt)
                    mma16816(acc[mt][nt], af[mt], &bf[nt >> 1][(nt & 1) * 2]);
            // lh: A1, reload B0
#pragma unroll
            for (int mt = 0; mt < 4; ++mt)
                ldsm4(af[mt], aB + (uint32_t)(SA_B + mt * 1024) + ac);
#pragma unroll
            for (int np = 0; np < 2; ++np)
                ldsm4(bf[np], bB + (uint32_t)(np * 1024) + bc);
#pragma unroll
            for (int mt = 0; mt < 4; ++mt)
#pragma unroll
                for (int nt = 0; nt < 4; ++nt)
                    mma16816(acc[mt][nt], af[mt], &bf[nt >> 1][(nt & 1) * 2]);
        }
        // ---- ks = 1 ----
        {
            const uint32_t ac = (uint32_t)(((a_chb + 2) ^ a_swz) << 4);
            const uint32_t bc = (uint32_t)(((b_chb + 2) ^ b_swz) << 4);
#pragma unroll
            for (int np = 0; np < 2; ++np)
                ldsm4(bf[np], bB + (uint32_t)(np * 1024) + bc);
#pragma unroll
            for (int mt = 0; mt < 4; ++mt)
                ldsm4(af[mt], aB + (uint32_t)(mt * 1024) + ac);
#pragma unroll
            for (int mt = 0; mt < 4; ++mt)
#pragma unroll
                for (int nt = 0; nt < 4; ++nt)
                    mma16816(acc[mt][nt], af[mt], &bf[nt >> 1][(nt & 1) * 2]);
#pragma unroll
            for (int np = 0; np < 2; ++np)
                ldsm4(bf[np], bB + (uint32_t)(SB_B + np * 1024) + bc);
#pragma unroll
            for (int mt = 0; mt < 4; ++mt)
#pragma unroll
                for (int nt = 0; nt < 4; ++nt)
                    mma16816(acc[mt][nt], af[mt], &bf[nt >> 1][(nt & 1) * 2]);
#pragma unroll
            for (int mt = 0; mt < 4; ++mt)
                ldsm4(af[mt], aB + (uint32_t)(SA_B + mt * 1024) + ac);
#pragma unroll
            for (int np = 0; np < 2; ++np)
                ldsm4(bf[np], bB + (uint32_t)(np * 1024) + bc);
#pragma unroll
            for (int mt = 0; mt < 4; ++mt)
#pragma unroll
                for (int nt = 0; nt < 4; ++nt)
                    mma16816(acc[mt][nt], af[mt], &bf[nt >> 1][(nt & 1) * 2]);
        }
    };

    load_stage(0, 0);
    load_stage(1, 1);

    static_assert(NS == 3 * 21 + 1, "stage unroll assumes NS==64");
#pragma unroll 1
    for (int i = 0; i < 21; ++i) {
        const int s = i * 3;
        stage_body(s + 0, 0, 2);
        stage_body(s + 1, 1, 0);
        stage_body(s + 2, 2, 1);
    }
    stage_body(NS - 1, 0, 2);

    // epilogue: bias + gelu + fp16 re-split of H (direct stores)
#pragma unroll
    for (int mt = 0; mt < 4; ++mt) {
        const int r0 = bm + warp_m * 64 + mt * 16 + (lane >> 2);
        const int r1 = r0 + 8;
#pragma unroll
        for (int nt = 0; nt < 4; ++nt) {
            const int cl = warp_n * 32 + nt * 8 + ((lane & 3) << 1);
            const int cg = bn + cl;
            const float bv0 = __ldg(bias + cg), bv1 = __ldg(bias + cg + 1);
            float v00 = SCL_A * gelu_exact(acc[mt][nt][0] * INV_SC + bv0);
            float v01 = SCL_A * gelu_exact(acc[mt][nt][1] * INV_SC + bv1);
            float v10 = SCL_A * gelu_exact(acc[mt][nt][2] * INV_SC + bv0);
            float v11 = SCL_A * gelu_exact(acc[mt][nt][3] * INV_SC + bv1);
            __half h00a, h00b, h01a, h01b, h10a, h10b, h11a, h11b;
            split2(v00, h00a, h00b); split2(v01, h01a, h01b);
            split2(v10, h10a, h10b); split2(v11, h11a, h11b);
            *(__half2*)(g_Hs0 + (size_t)r0 * DIM + cg) = __halves2half2(h00a, h01a);
            *(__half2*)(g_Hs1 + (size_t)r0 * DIM + cg) = __halves2half2(h00b, h01b);
            *(__half2*)(g_Hs0 + (size_t)r1 * DIM + cg) = __halves2half2(h10a, h11a);
            *(__half2*)(g_Hs1 + (size_t)r1 * DIM + cg) = __halves2half2(h10b, h11b);
        }
    }
}

// ---------------- GEMM2 + fused router + fused loss ----------------
__global__ __launch_bounds__(256, 2)
void k_gemm2r(const float* __restrict__ bias,
              float* __restrict__ out_rw, float* __restrict__ out_idx,
              float* __restrict__ out_loss, int write_idx) {
    constexpr int SA_B = 64 * 64;            // 4096 per split per stage
    constexpr int SB_B = 64 * 64;
    constexpr int STGB = 2 * SA_B + 2 * SB_B;  // 16384
    constexpr int RWL  = 66;                 // padded logits row (floats)

    extern __shared__ char sm[];
    __shared__ float psum_sh[NEXP];
    __shared__ int   cnt_sh[NEXP];
    __shared__ int   s_last;

    const int tid = threadIdx.x, wid = tid >> 5, lane = tid & 31;
    const int warp_m = wid >> 2, warp_n = wid & 3;
    const int bm = blockIdx.x * 64;
    const uint32_t smb = smem_u32(sm);

    if (tid < NEXP) { psum_sh[tid] = 0.0f; cnt_sh[tid] = 0; }

    const int lr = lane & 7, lg = lane >> 3;
    const int a_row = lr + (lg & 1) * 8;
    const int a_chb = lg >> 1;
    const int a_swz = (a_row >> 1) & 3;
    const int b_row = lr + (lg >> 1) * 8;
    const int b_chb = lg & 1;
    const int b_swz = (b_row >> 1) & 3;

    float acc[2][2][4];
#pragma unroll
    for (int i = 0; i < 2; ++i)
#pragma unroll
        for (int j = 0; j < 2; ++j)
#pragma unroll
            for (int e = 0; e < 4; ++e) acc[i][j][e] = 0.0f;

    auto load_stage = [&](int s, int buf) {
        const int k0 = s * KCH;
        const uint32_t base = smb + (uint32_t)(buf * STGB);
#pragma unroll
        for (int t = tid; t < 1024; t += 256) {
            if (t < 512) {
                int sp = t >> 8, idx = t & 255;
                int r = idx >> 2, c = idx & 3;
                const __half* src = (sp == 0 ? g_Hs0 : g_Hs1) + (size_t)(bm + r) * DIM + k0 + c * 8;
                cpa16(base + (uint32_t)(sp * SA_B + r * 64 + ((c ^ ((r >> 1) & 3)) << 4)), src);
            } else {
                int u = t - 512;
                int sp = u >> 8, idx = u & 255;
                int r = idx >> 2, c = idx & 3;
                const __half* src = (sp == 0 ? g_W2T0 : g_W2T1) + (size_t)r * DIM + k0 + c * 8;
                cpa16(base + (uint32_t)(2 * SA_B + sp * SB_B + r * 64 + ((c ^ ((r >> 1) & 3)) << 4)), src);
            }
        }
        cp_commit();
    };

    load_stage(0, 0);
    load_stage(1, 1);

    int rbuf = 0, wbuf = 2;
#pragma unroll 1
    for (int s = 0; s < NS; ++s) {
        cp_wait1();
        __syncthreads();

        if (s + 2 < NS) load_stage(s + 2, wbuf);
        else cp_commit();

        const uint32_t base = smb + (uint32_t)(rbuf * STGB);
        const uint32_t aB = base + (uint32_t)((warp_m * 32 + a_row) * 64);
        const uint32_t bB = base + 2 * SA_B + (uint32_t)((warp_n * 16 + b_row) * 64);

        uint32_t af[2][4], bf[4];
#pragma unroll
        for (int ks = 0; ks < 2; ++ks) {
            const uint32_t ac = (uint32_t)(((a_chb + 2 * ks) ^ a_swz) << 4);
            const uint32_t bc = (uint32_t)(((b_chb + 2 * ks) ^ b_swz) << 4);
            ldsm4(bf, bB + bc);
#pragma unroll
            for (int mt = 0; mt < 2; ++mt)
                ldsm4(af[mt], aB + (uint32_t)(mt * 1024) + ac);
#pragma unroll
            for (int mt = 0; mt < 2; ++mt)
#pragma unroll
                for (int nt = 0; nt < 2; ++nt)
                    mma16816(acc[mt][nt], af[mt], &bf[nt * 2]);
            ldsm4(bf, bB + (uint32_t)SB_B + bc);
#pragma unroll
            for (int mt = 0; mt < 2; ++mt)
#pragma unroll
                for (int nt = 0; nt < 2; ++nt)
                    mma16816(acc[mt][nt], af[mt], &bf[nt * 2]);
#pragma unroll
            for (int mt = 0; mt < 2; ++mt)
                ldsm4(af[mt], aB + (uint32_t)(SA_B + mt * 1024) + ac);
            ldsm4(bf, bB + bc);
#pragma unroll
            for (int mt = 0; mt < 2; ++mt)
#pragma unroll
                for (int nt = 0; nt < 2; ++nt)
                    mma16816(acc[mt][nt], af[mt], &bf[nt * 2]);
        }

        rbuf = (rbuf == 2) ? 0 : rbuf + 1;
        wbuf = (wbuf == 2) ? 0 : wbuf + 1;
    }

    // stage logits (bias added) into smem, reusing the ring space
    __syncthreads();
    float* sl = (float*)sm;   // 64 x 66 floats
#pragma unroll
    for (int mt = 0; mt < 2; ++mt) {
        const int r0 = warp_m * 32 + mt * 16 + (lane >> 2);
        const int r1 = r0 + 8;
#pragma unroll
        for (int nt = 0; nt < 2; ++nt) {
            const int cl = warp_n * 16 + nt * 8 + ((lane & 3) << 1);
            const float bv0 = __ldg(bias + cl), bv1 = __ldg(bias + cl + 1);
            sl[r0 * RWL + cl]     = acc[mt][nt][0] * INV_SC + bv0;
            sl[r0 * RWL + cl + 1] = acc[mt][nt][1] * INV_SC + bv1;
            sl[r1 * RWL + cl]     = acc[mt][nt][2] * INV_SC + bv0;
            sl[r1 * RWL + cl + 1] = acc[mt][nt][3] * INV_SC + bv1;
        }
    }
    __syncthreads();

    // fused router: each warp handles 8 tokens
    const float NEG_INF = __int_as_float(0xff800000);
#pragma unroll 1
    for (int tk = 0; tk < 8; ++tk) {
        const int t = wid * 8 + tk;
        float v0 = sl[t * RWL + lane];
        float v1 = sl[t * RWL + 32 + lane];

        float mx = fmaxf(v0, v1);
#pragma unroll
        for (int o = 16; o; o >>= 1) mx = fmaxf(mx, __shfl_xor_sync(0xffffffffu, mx, o));
        float p0 = expf(v0 - mx), p1 = expf(v1 - mx);
        float s = p0 + p1;
#pragma unroll
        for (int o = 16; o; o >>= 1) s += __shfl_xor_sync(0xffffffffu, s, o);
        float inv = 1.0f / s;
        atomicAdd(&psum_sh[lane], p0 * inv);
        atomicAdd(&psum_sh[lane + 32], p1 * inv);

        float w0 = v0, w1 = v1;
        float topv[TOPK]; int topi[TOPK];
#pragma unroll
        for (int k = 0; k < TOPK; ++k) {
            float bv; int bi;
            if (w0 >= w1) { bv = w0; bi = lane; } else { bv = w1; bi = lane + 32; }
#pragma unroll
            for (int o = 16; o; o >>= 1) {
                float ov = __shfl_xor_sync(0xffffffffu, bv, o);
                int   oi = __shfl_xor_sync(0xffffffffu, bi, o);
                if (ov > bv || (ov == bv && oi < bi)) { bv = ov; bi = oi; }
            }
            topv[k] = bv; topi[k] = bi;
            if (bi == lane) w0 = NEG_INF;
            if (bi == lane + 32) w1 = NEG_INF;
        }
        float es[TOPK], ss = 0.0f;
#pragma unroll
        for (int k = 0; k < TOPK; ++k) { es[k] = expf(topv[k] - topv[0]); ss += es[k]; }
        float invs = 1.0f / ss;
        float r0 = 0.0f, r1 = 0.0f;
#pragma unroll
        for (int k = 0; k < TOPK; ++k) {
            float w = es[k] * invs;
            if (topi[k] == lane) r0 = w;
            if (topi[k] == lane + 32) r1 = w;
        }
        const int tg = bm + t;
        out_rw[(size_t)tg * NEXP + lane]      = r0;
        out_rw[(size_t)tg * NEXP + 32 + lane] = r1;

        if (lane == 0) {
#pragma unroll
            for (int k = 0; k < TOPK; ++k) {
                if (write_idx) out_idx[(size_t)tg * TOPK + k] = (float)topi[k];
                atomicAdd(&cnt_sh[topi[k]], 1);
            }
        }
    }

    __syncthreads();
    if (tid < NEXP) {
        atomicAdd(&g_probsum[tid], psum_sh[tid]);
        atomicAdd(&g_cnt[tid], cnt_sh[tid]);
    }

    // last CTA computes the loss
    if (out_loss) {
        __threadfence();
        if (tid == 0) {
            int done = atomicAdd(&g_done, 1);
            s_last = (done == (int)gridDim.x - 1);
        }
        __syncthreads();
        if (s_last) {
            float* terms = (float*)sm;
            const float invN = 1.0f / (float)N_TOK;
            if (tid < NEXP)
                terms[tid] = ((float)g_cnt[tid] * invN) * (g_probsum[tid] * invN);
            __syncthreads();
            if (tid == 0) {
                float a = 0.0f;
                for (int i = 0; i < NEXP; ++i) a += terms[i];
                *out_loss = (float)NEXP * a;
            }
        }
    }
}

// ---------------- host launch ----------------
extern "C" void kernel_launch(void* const* d_in, const int* in_sizes, int n_in,
                              void* d_out, int out_size) {
    const float* x  = (const float*)d_in[0];
    const float* W1 = (const float*)d_in[1];
    const float* b1 = (const float*)d_in[2];
    const float* W2 = (const float*)d_in[3];
    const float* b2 = (const float*)d_in[4];

    float* out = (float*)d_out;
    float* out_rw = out;
    float* out_idx = nullptr;
    float* out_loss = nullptr;
    const long rw_elems = (long)N_TOK * NEXP;
    const long idx_elems = (long)N_TOK * TOPK;
    int has_idx = 0;
    if ((long)out_size >= rw_elems + idx_elems) { out_idx = out + rw_elems; has_idx = 1; }
    if ((long)out_size >= rw_elems + idx_elems + 1) out_loss = out + rw_elems + idx_elems;

    constexpr int SM1 = 3 * (2 * 128 * 64 + 2 * 128 * 64);  // 98304
    constexpr int SM2 = 3 * (2 * 64 * 64 + 2 * 64 * 64);    // 49152
    cudaFuncSetAttribute(k_mma1,   cudaFuncAttributeMaxDynamicSharedMemorySize, SM1);
    cudaFuncSetAttribute(k_gemm2r, cudaFuncAttributeMaxDynamicSharedMemorySize, SM2);

    k_prep<<<8320, 256>>>(x, W1, W2);

    k_mma1<<<dim3(16, 128), 256, SM1>>>(b1);

    k_gemm2r<<<dim3(256), 256, SM2>>>(b2, out_rw, out_idx, out_loss, has_idx);
}

// round 15
// speedup vs baseline: 1.0590x; 1.0440x over previous
#include <cuda_runtime.h>
#include <cuda_fp16.h>
#include <math.h>
#include <stdint.h>

constexpr int N_TOK = 16384;
constexpr int DIM   = 2048;
constexpr int NEXP  = 64;
constexpr int TOPK  = 8;
constexpr int KCH   = 32;          // K per stage
constexpr int NS    = DIM / KCH;   // 64 stages

// scales: X,H pre-scaled by 16; W1,W2 by 64; product scale 1024
constexpr float SCL_A  = 16.0f;
constexpr float SCL_B  = 64.0f;
constexpr float INV_SC = 1.0f / 1024.0f;

// ---------------- device scratch ----------------
__device__ __half g_Xs0[(size_t)N_TOK * DIM];
__device__ __half g_Xs1[(size_t)N_TOK * DIM];
__device__ __half g_Hs0[(size_t)N_TOK * DIM];
__device__ __half g_Hs1[(size_t)N_TOK * DIM];
__device__ __half g_W1T0[(size_t)DIM * DIM];   // [n][k]
__device__ __half g_W1T1[(size_t)DIM * DIM];
__device__ __half g_W2T0[(size_t)NEXP * DIM];  // [e][k]
__device__ __half g_W2T1[(size_t)NEXP * DIM];
__device__ float g_probsum[NEXP];
__device__ int   g_cnt[NEXP];

// ---------------- helpers ----------------
__device__ __forceinline__ float gelu_exact(float x) {
    return 0.5f * x * (1.0f + erff(x * 0.70710678118654752f));
}
__device__ __forceinline__ uint32_t smem_u32(const void* p) {
    uint32_t a;
    asm("{ .reg .u64 t; cvta.to.shared.u64 t, %1; cvt.u32.u64 %0, t; }" : "=r"(a) : "l"(p));
    return a;
}
__device__ __forceinline__ void cpa16(uint32_t dst, const void* src) {
    asm volatile("cp.async.cg.shared.global [%0], [%1], 16;" :: "r"(dst), "l"(src) : "memory");
}
__device__ __forceinline__ void cp_commit() {
    asm volatile("cp.async.commit_group;" ::: "memory");
}
__device__ __forceinline__ void cp_wait1() {
    asm volatile("cp.async.wait_group 1;" ::: "memory");
}
__device__ __forceinline__ void ldsm4(uint32_t* r, uint32_t a) {
    asm volatile("ldmatrix.sync.aligned.m8n8.x4.shared.b16 {%0,%1,%2,%3}, [%4];"
                 : "=r"(r[0]), "=r"(r[1]), "=r"(r[2]), "=r"(r[3]) : "r"(a));
}
__device__ __forceinline__ void mma16816(float* c, const uint32_t* a, const uint32_t* b) {
    asm volatile("mma.sync.aligned.m16n8k16.row.col.f32.f16.f16.f32 "
                 "{%0,%1,%2,%3}, {%4,%5,%6,%7}, {%8,%9}, {%0,%1,%2,%3};"
                 : "+f"(c[0]), "+f"(c[1]), "+f"(c[2]), "+f"(c[3])
                 : "r"(a[0]), "r"(a[1]), "r"(a[2]), "r"(a[3]), "r"(b[0]), "r"(b[1]));
}
__device__ __forceinline__ void split2(float v, __half& h0, __half& h1) {
    h0 = __float2half_rn(v);
    h1 = __float2half_rn(v - __half2float(h0));
}

// ---------------- fused preprocessing ----------------
// blocks [0,4096): split X; [4096,8192): transpose+split W1; [8192,8320): W2.
// block 8192 also zeroes the loss accumulators.
__global__ __launch_bounds__(256) void k_prep(const float* __restrict__ x,
                                              const float* __restrict__ W1,
                                              const float* __restrict__ W2) {
    __shared__ float t[32][33];
    const int b = blockIdx.x;
    const int tid = threadIdx.x;

    if (b < 4096) {
        const size_t total = (size_t)N_TOK * DIM / 4;
        for (size_t i = (size_t)b * 256 + tid; i < total; i += (size_t)4096 * 256) {
            float4 v = ((const float4*)x)[i];
            __half a0, a1, b0, b1, c0, c1, d0, d1;
            split2(SCL_A * v.x, a0, a1); split2(SCL_A * v.y, b0, b1);
            split2(SCL_A * v.z, c0, c1); split2(SCL_A * v.w, d0, d1);
            __half2 p0a = __halves2half2(a0, b0), p0b = __halves2half2(c0, d0);
            __half2 p1a = __halves2half2(a1, b1), p1b = __halves2half2(c1, d1);
            ((uint2*)g_Xs0)[i] = make_uint2(*(uint32_t*)&p0a, *(uint32_t*)&p0b);
            ((uint2*)g_Xs1)[i] = make_uint2(*(uint32_t*)&p1a, *(uint32_t*)&p1b);
        }
        return;
    }

    const float* src;
    __half *d0, *d1;
    int R, C, bx, by;
    if (b < 8192) {
        const int idx = b - 4096;
        src = W1; d0 = g_W1T0; d1 = g_W1T1; R = DIM; C = DIM;
        bx = (idx & 63) * 32; by = (idx >> 6) * 32;
    } else {
        if (b == 8192 && tid < NEXP) { g_probsum[tid] = 0.0f; g_cnt[tid] = 0; }
        const int idx = b - 8192;
        src = W2; d0 = g_W2T0; d1 = g_W2T1; R = DIM; C = NEXP;
        bx = (idx & 1) * 32; by = (idx >> 1) * 32;
    }
    const int tx = tid & 31, ty = tid >> 5;   // 32 x 8
#pragma unroll
    for (int i = 0; i < 32; i += 8)
        t[ty + i][tx] = src[(size_t)(by + ty + i) * C + bx + tx];
    __syncthreads();
#pragma unroll
    for (int i = 0; i < 32; i += 8) {
        float v = SCL_B * t[tx][ty + i];
        __half s0, s1; split2(v, s0, s1);
        size_t o = (size_t)(bx + ty + i) * R + by + tx;
        d0[o] = s0; d1[o] = s1;
    }
}

// ---------------- GEMM1: H = gelu(X@W1+b1), 128x128 tile, 3-stage ring ----------------
// C = A0*B0 + A0*B1 + A1*B0 (fp16 2-split, fp32 accum).
// 64B rows, chunk swizzle (c ^ ((r>>1)&3)).
// R11 inner loop, with the s+2 prefetch split in two halves (after hh of ks0 / ks1).
__global__ __launch_bounds__(256, 2)
void k_mma1(const float* __restrict__ bias) {
    constexpr int SA_B = 128 * 64;           // 8192 per split per stage
    constexpr int SB_B = 128 * 64;
    constexpr int STGB = 2 * SA_B + 2 * SB_B;

    extern __shared__ char sm[];
    const int tid = threadIdx.x, wid = tid >> 5, lane = tid & 31;
    const int warp_m = wid >> 2, warp_n = wid & 3;
    const int bm = blockIdx.y * 128;
    const int bn = blockIdx.x * 128;
    const uint32_t smb = smem_u32(sm);

    const int lr = lane & 7, lg = lane >> 3;
    const int a_row = lr + (lg & 1) * 8;
    const int a_chb = lg >> 1;
    const int a_swz = (a_row >> 1) & 3;
    const int b_row = lr + (lg >> 1) * 8;
    const int b_chb = lg & 1;
    const int b_swz = (b_row >> 1) & 3;

    float acc[4][4][4];
#pragma unroll
    for (int i = 0; i < 4; ++i)
#pragma unroll
        for (int j = 0; j < 4; ++j)
#pragma unroll
            for (int e = 0; e < 4; ++e) acc[i][j][e] = 0.0f;

    // half 0: A chunks (t in [0,1024)); half 1: B chunks (t in [1024,2048))
    auto load_half = [&](int s, int buf, int half) {
        const int k0 = s * KCH;
        const uint32_t base = smb + (uint32_t)(buf * STGB);
#pragma unroll
        for (int t = tid + half * 1024; t < (half + 1) * 1024; t += 256) {
            if (half == 0) {
                int sp = t >> 9, idx = t & 511;
                int r = idx >> 2, c = idx & 3;
                const __half* src = (sp == 0 ? g_Xs0 : g_Xs1) + (size_t)(bm + r) * DIM + k0 + c * 8;
                cpa16(base + (uint32_t)(sp * SA_B + r * 64 + ((c ^ ((r >> 1) & 3)) << 4)), src);
            } else {
                int u = t - 1024;
                int sp = u >> 9, idx = u & 511;
                int r = idx >> 2, c = idx & 3;
                const __half* src = (sp == 0 ? g_W1T0 : g_W1T1) + (size_t)(bn + r) * DIM + k0 + c * 8;
                cpa16(base + (uint32_t)(2 * SA_B + sp * SB_B + r * 64 + ((c ^ ((r >> 1) & 3)) << 4)), src);
            }
        }
    };
    auto load_stage = [&](int s, int buf) {
        load_half(s, buf, 0);
        load_half(s, buf, 1);
        cp_commit();
    };

    auto stage_body = [&](int s, int rb, int wb) {
        cp_wait1();
        __syncthreads();

        const uint32_t base = smb + (uint32_t)(rb * STGB);
        const uint32_t aB = base + (uint32_t)((warp_m * 64 + a_row) * 64);
        const uint32_t bB = base + 2 * SA_B + (uint32_t)((warp_n * 32 + b_row) * 64);

        uint32_t af[4][4], bf[2][4];
        // ---- ks = 0 ----
        {
            const uint32_t ac = (uint32_t)((a_chb ^ a_swz) << 4);
            const uint32_t bc = (uint32_t)((b_chb ^ b_swz) << 4);
#pragma unroll
            for (int np = 0; np < 2; ++np)
                ldsm4(bf[np], bB + (uint32_t)(np * 1024) + bc);
#pragma unroll
            for (int mt = 0; mt < 4; ++mt)
                ldsm4(af[mt], aB + (uint32_t)(mt * 1024) + ac);
#pragma unroll
            for (int mt = 0; mt < 4; ++mt)
#pragma unroll
                for (int nt = 0; nt < 4; ++nt)
                    mma16816(acc[mt][nt], af[mt], &bf[nt >> 1][(nt & 1) * 2]);

            // prefetch half 1 of 2 (A chunks) — tensor pipe has 64 mmas in flight
            if (s + 2 < NS) load_half(s + 2, wb, 0);

            // hl: B1, A0 resident
#pragma unroll
            for (int np = 0; np < 2; ++np)
                ldsm4(bf[np], bB + (uint32_t)(SB_B + np * 1024) + bc);
#pragma unroll
            for (int mt = 0; mt < 4; ++mt)
#pragma unroll
                for (int nt = 0; nt < 4; ++nt)
                    mma16816(acc[mt][nt], af[mt], &bf[nt >> 1][(nt & 1) * 2]);
            // lh: A1, reload B0
#pragma unroll
            for (int mt = 0; mt < 4; ++mt)
                ldsm4(af[mt], aB + (uint32_t)(SA_B + mt * 1024) + ac);
#pragma unroll
            for (int np = 0; np < 2; ++np)
                ldsm4(bf[np], bB + (uint32_t)(np * 1024) + bc);
#pragma unroll
            for (int mt = 0; mt < 4; ++mt)
#pragma unroll
                for (int nt = 0; nt < 4; ++nt)
                    mma16816(acc[mt][nt], af[mt], &bf[nt >> 1][(nt & 1) * 2]);
        }
        // ---- ks = 1 ----
        {
            const uint32_t ac = (uint32_t)(((a_chb + 2) ^ a_swz) << 4);
            const uint32_t bc = (uint32_t)(((b_chb + 2) ^ b_swz) << 4);
#pragma unroll
            for (int np = 0; np < 2; ++np)
                ldsm4(bf[np], bB + (uint32_t)(np * 1024) + bc);
#pragma unroll
            for (int mt = 0; mt < 4; ++mt)
                ldsm4(af[mt], aB + (uint32_t)(mt * 1024) + ac);
#pragma unroll
            for (int mt = 0; mt < 4; ++mt)
#pragma unroll
                for (int nt = 0; nt < 4; ++nt)
                    mma16816(acc[mt][nt], af[mt], &bf[nt >> 1][(nt & 1) * 2]);

            // prefetch half 2 of 2 (B chunks), then commit the group
            if (s + 2 < NS) load_half(s + 2, wb, 1);
            cp_commit();

#pragma unroll
            for (int np = 0; np < 2; ++np)
                ldsm4(bf[np], bB + (uint32_t)(SB_B + np * 1024) + bc);
#pragma unroll
            for (int mt = 0; mt < 4; ++mt)
#pragma unroll
                for (int nt = 0; nt < 4; ++nt)
                    mma16816(acc[mt][nt], af[mt], &bf[nt >> 1][(nt & 1) * 2]);
#pragma unroll
            for (int mt = 0; mt < 4; ++mt)
                ldsm4(af[mt], aB + (uint32_t)(SA_B + mt * 1024) + ac);
#pragma unroll
            for (int np = 0; np < 2; ++np)
                ldsm4(bf[np], bB + (uint32_t)(np * 1024) + bc);
#pragma unroll
            for (int mt = 0; mt < 4; ++mt)
#pragma unroll
                for (int nt = 0; nt < 4; ++nt)
                    mma16816(acc[mt][nt], af[mt], &bf[nt >> 1][(nt & 1) * 2]);
        }
    };

    load_stage(0, 0);
    load_stage(1, 1);

    static_assert(NS == 3 * 21 + 1, "stage unroll assumes NS==64");
#pragma unroll 1
    for (int i = 0; i < 21; ++i) {
        const int s = i * 3;
        stage_body(s + 0, 0, 2);
        stage_body(s + 1, 1, 0);
        stage_body(s + 2, 2, 1);
    }
    stage_body(NS - 1, 0, 2);

    // epilogue: bias + gelu + fp16 re-split of H (direct stores, measured best)
#pragma unroll
    for (int mt = 0; mt < 4; ++mt) {
        const int r0 = bm + warp_m * 64 + mt * 16 + (lane >> 2);
        const int r1 = r0 + 8;
#pragma unroll
        for (int nt = 0; nt < 4; ++nt) {
            const int cl = warp_n * 32 + nt * 8 + ((lane & 3) << 1);
            const int cg = bn + cl;
            const float bv0 = __ldg(bias + cg), bv1 = __ldg(bias + cg + 1);
            float v00 = SCL_A * gelu_exact(acc[mt][nt][0] * INV_SC + bv0);
            float v01 = SCL_A * gelu_exact(acc[mt][nt][1] * INV_SC + bv1);
            float v10 = SCL_A * gelu_exact(acc[mt][nt][2] * INV_SC + bv0);
            float v11 = SCL_A * gelu_exact(acc[mt][nt][3] * INV_SC + bv1);
            __half h00a, h00b, h01a, h01b, h10a, h10b, h11a, h11b;
            split2(v00, h00a, h00b); split2(v01, h01a, h01b);
            split2(v10, h10a, h10b); split2(v11, h11a, h11b);
            *(__half2*)(g_Hs0 + (size_t)r0 * DIM + cg) = __halves2half2(h00a, h01a);
            *(__half2*)(g_Hs1 + (size_t)r0 * DIM + cg) = __halves2half2(h00b, h01b);
            *(__half2*)(g_Hs0 + (size_t)r1 * DIM + cg) = __halves2half2(h10a, h11a);
            *(__half2*)(g_Hs1 + (size_t)r1 * DIM + cg) = __halves2half2(h10b, h11b);
        }
    }
}

// ---------------- GEMM2 + fused router: 64 tokens/CTA, all 64 experts ----------------
__global__ __launch_bounds__(256, 2)
void k_gemm2r(const float* __restrict__ bias,
              float* __restrict__ out_rw, float* __restrict__ out_idx, int write_idx) {
    constexpr int SA_B = 64 * 64;            // 4096 per split per stage
    constexpr int SB_B = 64 * 64;
    constexpr int STGB = 2 * SA_B + 2 * SB_B;  // 16384
    constexpr int RWL  = 66;                 // padded logits row (floats)

    extern __shared__ char sm[];
    __shared__ float psum_sh[NEXP];
    __shared__ int   cnt_sh[NEXP];

    const int tid = threadIdx.x, wid = tid >> 5, lane = tid & 31;
    const int warp_m = wid >> 2, warp_n = wid & 3;
    const int bm = blockIdx.x * 64;
    const uint32_t smb = smem_u32(sm);

    if (tid < NEXP) { psum_sh[tid] = 0.0f; cnt_sh[tid] = 0; }

    const int lr = lane & 7, lg = lane >> 3;
    const int a_row = lr + (lg & 1) * 8;
    const int a_chb = lg >> 1;
    const int a_swz = (a_row >> 1) & 3;
    const int b_row = lr + (lg >> 1) * 8;
    const int b_chb = lg & 1;
    const int b_swz = (b_row >> 1) & 3;

    float acc[2][2][4];
#pragma unroll
    for (int i = 0; i < 2; ++i)
#pragma unroll
        for (int j = 0; j < 2; ++j)
#pragma unroll
            for (int e = 0; e < 4; ++e) acc[i][j][e] = 0.0f;

    auto load_stage = [&](int s, int buf) {
        const int k0 = s * KCH;
        const uint32_t base = smb + (uint32_t)(buf * STGB);
#pragma unroll
        for (int t = tid; t < 1024; t += 256) {
            if (t < 512) {
                int sp = t >> 8, idx = t & 255;
                int r = idx >> 2, c = idx & 3;
                const __half* src = (sp == 0 ? g_Hs0 : g_Hs1) + (size_t)(bm + r) * DIM + k0 + c * 8;
                cpa16(base + (uint32_t)(sp * SA_B + r * 64 + ((c ^ ((r >> 1) & 3)) << 4)), src);
            } else {
                int u = t - 512;
                int sp = u >> 8, idx = u & 255;
                int r = idx >> 2, c = idx & 3;
                const __half* src = (sp == 0 ? g_W2T0 : g_W2T1) + (size_t)r * DIM + k0 + c * 8;
                cpa16(base + (uint32_t)(2 * SA_B + sp * SB_B + r * 64 + ((c ^ ((r >> 1) & 3)) << 4)), src);
            }
        }
        cp_commit();
    };

    load_stage(0, 0);
    load_stage(1, 1);

    int rbuf = 0, wbuf = 2;
#pragma unroll 1
    for (int s = 0; s < NS; ++s) {
        cp_wait1();
        __syncthreads();

        if (s + 2 < NS) load_stage(s + 2, wbuf);
        else cp_commit();

        const uint32_t base = smb + (uint32_t)(rbuf * STGB);
        const uint32_t aB = base + (uint32_t)((warp_m * 32 + a_row) * 64);
        const uint32_t bB = base + 2 * SA_B + (uint32_t)((warp_n * 16 + b_row) * 64);

        uint32_t af[2][4], bf[4];
#pragma unroll
        for (int ks = 0; ks < 2; ++ks) {
            const uint32_t ac = (uint32_t)(((a_chb + 2 * ks) ^ a_swz) << 4);
            const uint32_t bc = (uint32_t)(((b_chb + 2 * ks) ^ b_swz) << 4);
            ldsm4(bf, bB + bc);
#pragma unroll
            for (int mt = 0; mt < 2; ++mt)
                ldsm4(af[mt], aB + (uint32_t)(mt * 1024) + ac);
#pragma unroll
            for (int mt = 0; mt < 2; ++mt)
#pragma unroll
                for (int nt = 0; nt < 2; ++nt)
                    mma16816(acc[mt][nt], af[mt], &bf[nt * 2]);
            ldsm4(bf, bB + (uint32_t)SB_B + bc);
#pragma unroll
            for (int mt = 0; mt < 2; ++mt)
#pragma unroll
                for (int nt = 0; nt < 2; ++nt)
                    mma16816(acc[mt][nt], af[mt], &bf[nt * 2]);
#pragma unroll
            for (int mt = 0; mt < 2; ++mt)
                ldsm4(af[mt], aB + (uint32_t)(SA_B + mt * 1024) + ac);
            ldsm4(bf, bB + bc);
#pragma unroll
            for (int mt = 0; mt < 2; ++mt)
#pragma unroll
                for (int nt = 0; nt < 2; ++nt)
                    mma16816(acc[mt][nt], af[mt], &bf[nt * 2]);
        }

        rbuf = (rbuf == 2) ? 0 : rbuf + 1;
        wbuf = (wbuf == 2) ? 0 : wbuf + 1;
    }

    // stage logits (bias added) into smem, reusing the ring space
    __syncthreads();
    float* sl = (float*)sm;   // 64 x 66 floats
#pragma unroll
    for (int mt = 0; mt < 2; ++mt) {
        const int r0 = warp_m * 32 + mt * 16 + (lane >> 2);
        const int r1 = r0 + 8;
#pragma unroll
        for (int nt = 0; nt < 2; ++nt) {
            const int cl = warp_n * 16 + nt * 8 + ((lane & 3) << 1);
            const float bv0 = __ldg(bias + cl), bv1 = __ldg(bias + cl + 1);
            sl[r0 * RWL + cl]     = acc[mt][nt][0] * INV_SC + bv0;
            sl[r0 * RWL + cl + 1] = acc[mt][nt][1] * INV_SC + bv1;
            sl[r1 * RWL + cl]     = acc[mt][nt][2] * INV_SC + bv0;
            sl[r1 * RWL + cl + 1] = acc[mt][nt][3] * INV_SC + bv1;
        }
    }
    __syncthreads();

    // fused router: each warp handles 8 tokens
    const float NEG_INF = __int_as_float(0xff800000);
#pragma unroll 1
    for (int tk = 0; tk < 8; ++tk) {
        const int t = wid * 8 + tk;
        float v0 = sl[t * RWL + lane];
        float v1 = sl[t * RWL + 32 + lane];

        float mx = fmaxf(v0, v1);
#pragma unroll
        for (int o = 16; o; o >>= 1) mx = fmaxf(mx, __shfl_xor_sync(0xffffffffu, mx, o));
        float p0 = expf(v0 - mx), p1 = expf(v1 - mx);
        float s = p0 + p1;
#pragma unroll
        for (int o = 16; o; o >>= 1) s += __shfl_xor_sync(0xffffffffu, s, o);
        float inv = 1.0f / s;
        atomicAdd(&psum_sh[lane], p0 * inv);
        atomicAdd(&psum_sh[lane + 32], p1 * inv);

        float w0 = v0, w1 = v1;
        float topv[TOPK]; int topi[TOPK];
#pragma unroll
        for (int k = 0; k < TOPK; ++k) {
            float bv; int bi;
            if (w0 >= w1) { bv = w0; bi = lane; } else { bv = w1; bi = lane + 32; }
#pragma unroll
            for (int o = 16; o; o >>= 1) {
                float ov = __shfl_xor_sync(0xffffffffu, bv, o);
                int   oi = __shfl_xor_sync(0xffffffffu, bi, o);
                if (ov > bv || (ov == bv && oi < bi)) { bv = ov; bi = oi; }
            }
            topv[k] = bv; topi[k] = bi;
            if (bi == lane) w0 = NEG_INF;
            if (bi == lane + 32) w1 = NEG_INF;
        }
        float es[TOPK], ss = 0.0f;
#pragma unroll
        for (int k = 0; k < TOPK; ++k) { es[k] = expf(topv[k] - topv[0]); ss += es[k]; }
        float invs = 1.0f / ss;
        float r0 = 0.0f, r1 = 0.0f;
#pragma unroll
        for (int k = 0; k < TOPK; ++k) {
            float w = es[k] * invs;
            if (topi[k] == lane) r0 = w;
            if (topi[k] == lane + 32) r1 = w;
        }
        const int tg = bm + t;
        out_rw[(size_t)tg * NEXP + lane]      = r0;
        out_rw[(size_t)tg * NEXP + 32 + lane] = r1;

        if (lane == 0) {
#pragma unroll
            for (int k = 0; k < TOPK; ++k) {
                if (write_idx) out_idx[(size_t)tg * TOPK + k] = (float)topi[k];
                atomicAdd(&cnt_sh[topi[k]], 1);
            }
        }
    }

    __syncthreads();
    if (tid < NEXP) {
        atomicAdd(&g_probsum[tid], psum_sh[tid]);
        atomicAdd(&g_cnt[tid], cnt_sh[tid]);
    }
}

// ---------------- loss ----------------
__global__ void k_loss(float* __restrict__ out_loss) {
    __shared__ float sh[NEXP];
    int e = threadIdx.x;
    float invN = 1.0f / (float)N_TOK;
    sh[e] = ((float)g_cnt[e] * invN) * (g_probsum[e] * invN);
    __syncthreads();
    if (e < 32) sh[e] += sh[e + 32];
    __syncthreads();
    if (e == 0) {
        float acc = 0.0f;
        for (int i = 0; i < 32; ++i) acc += sh[i];
        *out_loss = (float)NEXP * acc;
    }
}

// ---------------- host launch ----------------
extern "C" void kernel_launch(void* const* d_in, const int* in_sizes, int n_in,
                              void* d_out, int out_size) {
    const float* x  = (const float*)d_in[0];
    const float* W1 = (const float*)d_in[1];
    const float* b1 = (const float*)d_in[2];
    const float* W2 = (const float*)d_in[3];
    const float* b2 = (const float*)d_in[4];

    float* out = (float*)d_out;
    float* out_rw = out;
    float* out_idx = nullptr;
    float* out_loss = nullptr;
    const long rw_elems = (long)N_TOK * NEXP;
    const long idx_elems = (long)N_TOK * TOPK;
    int has_idx = 0;
    if ((long)out_size >= rw_elems + idx_elems) { out_idx = out + rw_elems; has_idx = 1; }
    if ((long)out_size >= rw_elems + idx_elems + 1) out_loss = out + rw_elems + idx_elems;

    constexpr int SM1 = 3 * (2 * 128 * 64 + 2 * 128 * 64);  // 98304
    constexpr int SM2 = 3 * (2 * 64 * 64 + 2 * 64 * 64);    // 49152
    cudaFuncSetAttribute(k_mma1,   cudaFuncAttributeMaxDynamicSharedMemorySize, SM1);
    cudaFuncSetAttribute(k_gemm2r, cudaFuncAttributeMaxDynamicSharedMemorySize, SM2);

    k_prep<<<8320, 256>>>(x, W1, W2);

    k_mma1<<<dim3(16, 128), 256, SM1>>>(b1);

    k_gemm2r<<<dim3(256), 256, SM2>>>(b2, out_rw, out_idx, has_idx);

    if (out_loss) k_loss<<<1, 64>>>(out_loss);
}

// round 16
// speedup vs baseline: 1.0711x; 1.0115x over previous
#include <cuda_runtime.h>
#include <cuda_fp16.h>
#include <math.h>
#include <stdint.h>

constexpr int N_TOK = 16384;
constexpr int DIM   = 2048;
constexpr int NEXP  = 64;
constexpr int TOPK  = 8;
constexpr int KCH   = 32;          // K per stage
constexpr int NS    = DIM / KCH;   // 64 stages

// scales: X,H pre-scaled by 16; W1,W2 by 64; product scale 1024
constexpr float SCL_A  = 16.0f;
constexpr float SCL_B  = 64.0f;
constexpr float INV_SC = 1.0f / 1024.0f;

// ---------------- device scratch ----------------
__device__ __half g_Xs0[(size_t)N_TOK * DIM];
__device__ __half g_Xs1[(size_t)N_TOK * DIM];
__device__ __half g_Hs0[(size_t)N_TOK * DIM];
__device__ __half g_Hs1[(size_t)N_TOK * DIM];
__device__ __half g_W1T0[(size_t)DIM * DIM];   // [n][k]
__device__ __half g_W1T1[(size_t)DIM * DIM];
__device__ __half g_W2T0[(size_t)NEXP * DIM];  // [e][k]
__device__ __half g_W2T1[(size_t)NEXP * DIM];
__device__ float g_probsum[NEXP];
__device__ int   g_cnt[NEXP];

// ---------------- helpers ----------------
__device__ __forceinline__ float gelu_exact(float x) {
    return 0.5f * x * (1.0f + erff(x * 0.70710678118654752f));
}
__device__ __forceinline__ uint32_t smem_u32(const void* p) {
    uint32_t a;
    asm("{ .reg .u64 t; cvta.to.shared.u64 t, %1; cvt.u32.u64 %0, t; }" : "=r"(a) : "l"(p));
    return a;
}
__device__ __forceinline__ void cpa16(uint32_t dst, const void* src) {
    asm volatile("cp.async.cg.shared.global [%0], [%1], 16;" :: "r"(dst), "l"(src) : "memory");
}
__device__ __forceinline__ void cp_commit() {
    asm volatile("cp.async.commit_group;" ::: "memory");
}
__device__ __forceinline__ void cp_wait1() {
    asm volatile("cp.async.wait_group 1;" ::: "memory");
}
__device__ __forceinline__ void ldsm4(uint32_t* r, uint32_t a) {
    asm volatile("ldmatrix.sync.aligned.m8n8.x4.shared.b16 {%0,%1,%2,%3}, [%4];"
                 : "=r"(r[0]), "=r"(r[1]), "=r"(r[2]), "=r"(r[3]) : "r"(a));
}
__device__ __forceinline__ void mma16816(float* c, const uint32_t* a, const uint32_t* b) {
    asm volatile("mma.sync.aligned.m16n8k16.row.col.f32.f16.f16.f32 "
                 "{%0,%1,%2,%3}, {%4,%5,%6,%7}, {%8,%9}, {%0,%1,%2,%3};"
                 : "+f"(c[0]), "+f"(c[1]), "+f"(c[2]), "+f"(c[3])
                 : "r"(a[0]), "r"(a[1]), "r"(a[2]), "r"(a[3]), "r"(b[0]), "r"(b[1]));
}
__device__ __forceinline__ void split2(float v, __half& h0, __half& h1) {
    h0 = __float2half_rn(v);
    h1 = __float2half_rn(v - __half2float(h0));
}

// ---------------- fused preprocessing ----------------
// blocks [0,4096): split X; [4096,8192): transpose+split W1; [8192,8320): W2.
// block 8192 also zeroes the loss accumulators.
__global__ __launch_bounds__(256) void k_prep(const float* __restrict__ x,
                                              const float* __restrict__ W1,
                                              const float* __restrict__ W2) {
    __shared__ float t[32][33];
    const int b = blockIdx.x;
    const int tid = threadIdx.x;

    if (b < 4096) {
        const size_t total = (size_t)N_TOK * DIM / 4;
        for (size_t i = (size_t)b * 256 + tid; i < total; i += (size_t)4096 * 256) {
            float4 v = ((const float4*)x)[i];
            __half a0, a1, b0, b1, c0, c1, d0, d1;
            split2(SCL_A * v.x, a0, a1); split2(SCL_A * v.y, b0, b1);
            split2(SCL_A * v.z, c0, c1); split2(SCL_A * v.w, d0, d1);
            __half2 p0a = __halves2half2(a0, b0), p0b = __halves2half2(c0, d0);
            __half2 p1a = __halves2half2(a1, b1), p1b = __halves2half2(c1, d1);
            ((uint2*)g_Xs0)[i] = make_uint2(*(uint32_t*)&p0a, *(uint32_t*)&p0b);
            ((uint2*)g_Xs1)[i] = make_uint2(*(uint32_t*)&p1a, *(uint32_t*)&p1b);
        }
        return;
    }

    const float* src;
    __half *d0, *d1;
    int R, C, bx, by;
    if (b < 8192) {
        const int idx = b - 4096;
        src = W1; d0 = g_W1T0; d1 = g_W1T1; R = DIM; C = DIM;
        bx = (idx & 63) * 32; by = (idx >> 6) * 32;
    } else {
        if (b == 8192 && tid < NEXP) { g_probsum[tid] = 0.0f; g_cnt[tid] = 0; }
        const int idx = b - 8192;
        src = W2; d0 = g_W2T0; d1 = g_W2T1; R = DIM; C = NEXP;
        bx = (idx & 1) * 32; by = (idx >> 1) * 32;
    }
    const int tx = tid & 31, ty = tid >> 5;   // 32 x 8
#pragma unroll
    for (int i = 0; i < 32; i += 8)
        t[ty + i][tx] = src[(size_t)(by + ty + i) * C + bx + tx];
    __syncthreads();
#pragma unroll
    for (int i = 0; i < 32; i += 8) {
        float v = SCL_B * t[tx][ty + i];
        __half s0, s1; split2(v, s0, s1);
        size_t o = (size_t)(bx + ty + i) * R + by + tx;
        d0[o] = s0; d1[o] = s1;
    }
}

// ---------------- GEMM1: H = gelu(X@W1+b1), 128x128 tile, 3-stage ring ----------------
// C = A0*B0 + A0*B1 + A1*B0 (fp16 2-split, fp32 accum).
// 64B rows, chunk swizzle (c ^ ((r>>1)&3)).
// R15 structure with the s+2 prefetch split into QUARTERS, one behind each
// 16-mma run (hh-ks0, hl-ks0, hh-ks1, hl-ks1 + commit).
__global__ __launch_bounds__(256, 2)
void k_mma1(const float* __restrict__ bias) {
    constexpr int SA_B = 128 * 64;           // 8192 per split per stage
    constexpr int SB_B = 128 * 64;
    constexpr int STGB = 2 * SA_B + 2 * SB_B;

    extern __shared__ char sm[];
    const int tid = threadIdx.x, wid = tid >> 5, lane = tid & 31;
    const int warp_m = wid >> 2, warp_n = wid & 3;
    const int bm = blockIdx.y * 128;
    const int bn = blockIdx.x * 128;
    const uint32_t smb = smem_u32(sm);

    const int lr = lane & 7, lg = lane >> 3;
    const int a_row = lr + (lg & 1) * 8;
    const int a_chb = lg >> 1;
    const int a_swz = (a_row >> 1) & 3;
    const int b_row = lr + (lg >> 1) * 8;
    const int b_chb = lg & 1;
    const int b_swz = (b_row >> 1) & 3;

    float acc[4][4][4];
#pragma unroll
    for (int i = 0; i < 4; ++i)
#pragma unroll
        for (int j = 0; j < 4; ++j)
#pragma unroll
            for (int e = 0; e < 4; ++e) acc[i][j][e] = 0.0f;

    // quarter q: q0 = A split0, q1 = A split1, q2 = B split0, q3 = B split1.
    // Each quarter is 512 16B chunks (2 cp.async per thread).
    auto load_quarter = [&](int s, int buf, int q) {
        const int k0 = s * KCH;
        const uint32_t base = smb + (uint32_t)(buf * STGB);
#pragma unroll
        for (int u = tid; u < 512; u += 256) {
            int r = u >> 2, c = u & 3;
            const uint32_t sw = (uint32_t)(r * 64 + ((c ^ ((r >> 1) & 3)) << 4));
            if (q == 0) {
                cpa16(base + sw, g_Xs0 + (size_t)(bm + r) * DIM + k0 + c * 8);
            } else if (q == 1) {
                cpa16(base + (uint32_t)SA_B + sw, g_Xs1 + (size_t)(bm + r) * DIM + k0 + c * 8);
            } else if (q == 2) {
                cpa16(base + (uint32_t)(2 * SA_B) + sw, g_W1T0 + (size_t)(bn + r) * DIM + k0 + c * 8);
            } else {
                cpa16(base + (uint32_t)(2 * SA_B + SB_B) + sw, g_W1T1 + (size_t)(bn + r) * DIM + k0 + c * 8);
            }
        }
    };
    auto load_stage = [&](int s, int buf) {
#pragma unroll
        for (int q = 0; q < 4; ++q) load_quarter(s, buf, q);
        cp_commit();
    };

    auto stage_body = [&](int s, int rb, int wb) {
        cp_wait1();
        __syncthreads();

        const uint32_t base = smb + (uint32_t)(rb * STGB);
        const uint32_t aB = base + (uint32_t)((warp_m * 64 + a_row) * 64);
        const uint32_t bB = base + 2 * SA_B + (uint32_t)((warp_n * 32 + b_row) * 64);
        const bool pf = (s + 2 < NS);

        uint32_t af[4][4], bf[2][4];
        // ---- ks = 0 ----
        {
            const uint32_t ac = (uint32_t)((a_chb ^ a_swz) << 4);
            const uint32_t bc = (uint32_t)((b_chb ^ b_swz) << 4);
#pragma unroll
            for (int np = 0; np < 2; ++np)
                ldsm4(bf[np], bB + (uint32_t)(np * 1024) + bc);
#pragma unroll
            for (int mt = 0; mt < 4; ++mt)
                ldsm4(af[mt], aB + (uint32_t)(mt * 1024) + ac);
#pragma unroll
            for (int mt = 0; mt < 4; ++mt)
#pragma unroll
                for (int nt = 0; nt < 4; ++nt)
                    mma16816(acc[mt][nt], af[mt], &bf[nt >> 1][(nt & 1) * 2]);

            if (pf) load_quarter(s + 2, wb, 0);   // A split0

            // hl: B1, A0 resident
#pragma unroll
            for (int np = 0; np < 2; ++np)
                ldsm4(bf[np], bB + (uint32_t)(SB_B + np * 1024) + bc);
#pragma unroll
            for (int mt = 0; mt < 4; ++mt)
#pragma unroll
                for (int nt = 0; nt < 4; ++nt)
                    mma16816(acc[mt][nt], af[mt], &bf[nt >> 1][(nt & 1) * 2]);

            if (pf) load_quarter(s + 2, wb, 1);   // A split1

            // lh: A1, reload B0
#pragma unroll
            for (int mt = 0; mt < 4; ++mt)
                ldsm4(af[mt], aB + (uint32_t)(SA_B + mt * 1024) + ac);
#pragma unroll
            for (int np = 0; np < 2; ++np)
                ldsm4(bf[np], bB + (uint32_t)(np * 1024) + bc);
#pragma unroll
            for (int mt = 0; mt < 4; ++mt)
#pragma unroll
                for (int nt = 0; nt < 4; ++nt)
                    mma16816(acc[mt][nt], af[mt], &bf[nt >> 1][(nt & 1) * 2]);
        }
        // ---- ks = 1 ----
        {
            const uint32_t ac = (uint32_t)(((a_chb + 2) ^ a_swz) << 4);
            const uint32_t bc = (uint32_t)(((b_chb + 2) ^ b_swz) << 4);
#pragma unroll
            for (int np = 0; np < 2; ++np)
                ldsm4(bf[np], bB + (uint32_t)(np * 1024) + bc);
#pragma unroll
            for (int mt = 0; mt < 4; ++mt)
                ldsm4(af[mt], aB + (uint32_t)(mt * 1024) + ac);
#pragma unroll
            for (int mt = 0; mt < 4; ++mt)
#pragma unroll
                for (int nt = 0; nt < 4; ++nt)
                    mma16816(acc[mt][nt], af[mt], &bf[nt >> 1][(nt & 1) * 2]);

            if (pf) load_quarter(s + 2, wb, 2);   // B split0

#pragma unroll
            for (int np = 0; np < 2; ++np)
                ldsm4(bf[np], bB + (uint32_t)(SB_B + np * 1024) + bc);
#pragma unroll
            for (int mt = 0; mt < 4; ++mt)
#pragma unroll
                for (int nt = 0; nt < 4; ++nt)
                    mma16816(acc[mt][nt], af[mt], &bf[nt >> 1][(nt & 1) * 2]);

            if (pf) load_quarter(s + 2, wb, 3);   // B split1
            cp_commit();                          // one group per stage, always

#pragma unroll
            for (int mt = 0; mt < 4; ++mt)
                ldsm4(af[mt], aB + (uint32_t)(SA_B + mt * 1024) + ac);
#pragma unroll
            for (int np = 0; np < 2; ++np)
                ldsm4(bf[np], bB + (uint32_t)(np * 1024) + bc);
#pragma unroll
            for (int mt = 0; mt < 4; ++mt)
#pragma unroll
                for (int nt = 0; nt < 4; ++nt)
                    mma16816(acc[mt][nt], af[mt], &bf[nt >> 1][(nt & 1) * 2]);
        }
    };

    load_stage(0, 0);
    load_stage(1, 1);

    static_assert(NS == 3 * 21 + 1, "stage unroll assumes NS==64");
#pragma unroll 1
    for (int i = 0; i < 21; ++i) {
        const int s = i * 3;
        stage_body(s + 0, 0, 2);
        stage_body(s + 1, 1, 0);
        stage_body(s + 2, 2, 1);
    }
    stage_body(NS - 1, 0, 2);

    // epilogue: bias + gelu + fp16 re-split of H (direct stores, measured best)
#pragma unroll
    for (int mt = 0; mt < 4; ++mt) {
        const int r0 = bm + warp_m * 64 + mt * 16 + (lane >> 2);
        const int r1 = r0 + 8;
#pragma unroll
        for (int nt = 0; nt < 4; ++nt) {
            const int cl = warp_n * 32 + nt * 8 + ((lane & 3) << 1);
            const int cg = bn + cl;
            const float bv0 = __ldg(bias + cg), bv1 = __ldg(bias + cg + 1);
            float v00 = SCL_A * gelu_exact(acc[mt][nt][0] * INV_SC + bv0);
            float v01 = SCL_A * gelu_exact(acc[mt][nt][1] * INV_SC + bv1);
            float v10 = SCL_A * gelu_exact(acc[mt][nt][2] * INV_SC + bv0);
            float v11 = SCL_A * gelu_exact(acc[mt][nt][3] * INV_SC + bv1);
            __half h00a, h00b, h01a, h01b, h10a, h10b, h11a, h11b;
            split2(v00, h00a, h00b); split2(v01, h01a, h01b);
            split2(v10, h10a, h10b); split2(v11, h11a, h11b);
            *(__half2*)(g_Hs0 + (size_t)r0 * DIM + cg) = __halves2half2(h00a, h01a);
            *(__half2*)(g_Hs1 + (size_t)r0 * DIM + cg) = __halves2half2(h00b, h01b);
            *(__half2*)(g_Hs0 + (size_t)r1 * DIM + cg) = __halves2half2(h10a, h11a);
            *(__half2*)(g_Hs1 + (size_t)r1 * DIM + cg) = __halves2half2(h10b, h11b);
        }
    }
}

// ---------------- GEMM2 + fused router: 64 tokens/CTA, all 64 experts ----------------
// Prefetch for s+2 split in halves behind the first mma block of each ks.
__global__ __launch_bounds__(256, 2)
void k_gemm2r(const float* __restrict__ bias,
              float* __restrict__ out_rw, float* __restrict__ out_idx, int write_idx) {
    constexpr int SA_B = 64 * 64;            // 4096 per split per stage
    constexpr int SB_B = 64 * 64;
    constexpr int STGB = 2 * SA_B + 2 * SB_B;  // 16384
    constexpr int RWL  = 66;                 // padded logits row (floats)

    extern __shared__ char sm[];
    __shared__ float psum_sh[NEXP];
    __shared__ int   cnt_sh[NEXP];

    const int tid = threadIdx.x, wid = tid >> 5, lane = tid & 31;
    const int warp_m = wid >> 2, warp_n = wid & 3;
    const int bm = blockIdx.x * 64;
    const uint32_t smb = smem_u32(sm);

    if (tid < NEXP) { psum_sh[tid] = 0.0f; cnt_sh[tid] = 0; }

    const int lr = lane & 7, lg = lane >> 3;
    const int a_row = lr + (lg & 1) * 8;
    const int a_chb = lg >> 1;
    const int a_swz = (a_row >> 1) & 3;
    const int b_row = lr + (lg >> 1) * 8;
    const int b_chb = lg & 1;
    const int b_swz = (b_row >> 1) & 3;

    float acc[2][2][4];
#pragma unroll
    for (int i = 0; i < 2; ++i)
#pragma unroll
        for (int j = 0; j < 2; ++j)
#pragma unroll
            for (int e = 0; e < 4; ++e) acc[i][j][e] = 0.0f;

    // half 0: A chunks (512), half 1: B chunks (512)
    auto load_half = [&](int s, int buf, int half) {
        const int k0 = s * KCH;
        const uint32_t base = smb + (uint32_t)(buf * STGB);
#pragma unroll
        for (int u = tid; u < 512; u += 256) {
            int sp = u >> 8, idx = u & 255;
            int r = idx >> 2, c = idx & 3;
            const uint32_t sw = (uint32_t)(r * 64 + ((c ^ ((r >> 1) & 3)) << 4));
            if (half == 0) {
                const __half* src = (sp == 0 ? g_Hs0 : g_Hs1) + (size_t)(bm + r) * DIM + k0 + c * 8;
                cpa16(base + (uint32_t)(sp * SA_B) + sw, src);
            } else {
                const __half* src = (sp == 0 ? g_W2T0 : g_W2T1) + (size_t)r * DIM + k0 + c * 8;
                cpa16(base + (uint32_t)(2 * SA_B + sp * SB_B) + sw, src);
            }
        }
    };
    auto load_stage = [&](int s, int buf) {
        load_half(s, buf, 0);
        load_half(s, buf, 1);
        cp_commit();
    };

    load_stage(0, 0);
    load_stage(1, 1);

    int rbuf = 0, wbuf = 2;
#pragma unroll 1
    for (int s = 0; s < NS; ++s) {
        cp_wait1();
        __syncthreads();

        const bool pf = (s + 2 < NS);
        const uint32_t base = smb + (uint32_t)(rbuf * STGB);
        const uint32_t aB = base + (uint32_t)((warp_m * 32 + a_row) * 64);
        const uint32_t bB = base + 2 * SA_B + (uint32_t)((warp_n * 16 + b_row) * 64);

        uint32_t af[2][4], bf[4];
#pragma unroll
        for (int ks = 0; ks < 2; ++ks) {
            const uint32_t ac = (uint32_t)(((a_chb + 2 * ks) ^ a_swz) << 4);
            const uint32_t bc = (uint32_t)(((b_chb + 2 * ks) ^ b_swz) << 4);
            ldsm4(bf, bB + bc);
#pragma unroll
            for (int mt = 0; mt < 2; ++mt)
                ldsm4(af[mt], aB + (uint32_t)(mt * 1024) + ac);
#pragma unroll
            for (int mt = 0; mt < 2; ++mt)
#pragma unroll
                for (int nt = 0; nt < 2; ++nt)
                    mma16816(acc[mt][nt], af[mt], &bf[nt * 2]);

            if (pf) load_half(s + 2, wbuf, ks);   // A half after ks0 hh, B half after ks1 hh
            if (ks == 1) cp_commit();

            ldsm4(bf, bB + (uint32_t)SB_B + bc);
#pragma unroll
            for (int mt = 0; mt < 2; ++mt)
#pragma unroll
                for (int nt = 0; nt < 2; ++nt)
                    mma16816(acc[mt][nt], af[mt], &bf[nt * 2]);
#pragma unroll
            for (int mt = 0; mt < 2; ++mt)
                ldsm4(af[mt], aB + (uint32_t)(SA_B + mt * 1024) + ac);
            ldsm4(bf, bB + bc);
#pragma unroll
            for (int mt = 0; mt < 2; ++mt)
#pragma unroll
                for (int nt = 0; nt < 2; ++nt)
                    mma16816(acc[mt][nt], af[mt], &bf[nt * 2]);
        }

        rbuf = (rbuf == 2) ? 0 : rbuf + 1;
        wbuf = (wbuf == 2) ? 0 : wbuf + 1;
    }

    // stage logits (bias added) into smem, reusing the ring space
    __syncthreads();
    float* sl = (float*)sm;   // 64 x 66 floats
#pragma unroll
    for (int mt = 0; mt < 2; ++mt) {
        const int r0 = warp_m * 32 + mt * 16 + (lane >> 2);
        const int r1 = r0 + 8;
#pragma unroll
        for (int nt = 0; nt < 2; ++nt) {
            const int cl = warp_n * 16 + nt * 8 + ((lane & 3) << 1);
            const float bv0 = __ldg(bias + cl), bv1 = __ldg(bias + cl + 1);
            sl[r0 * RWL + cl]     = acc[mt][nt][0] * INV_SC + bv0;
            sl[r0 * RWL + cl + 1] = acc[mt][nt][1] * INV_SC + bv1;
            sl[r1 * RWL + cl]     = acc[mt][nt][2] * INV_SC + bv0;
            sl[r1 * RWL + cl + 1] = acc[mt][nt][3] * INV_SC + bv1;
        }
    }
    __syncthreads();

    // fused router: each warp handles 8 tokens
    const float NEG_INF = __int_as_float(0xff800000);
#pragma unroll 1
    for (int tk = 0; tk < 8; ++tk) {
        const int t = wid * 8 + tk;
        float v0 = sl[t * RWL + lane];
        float v1 = sl[t * RWL + 32 + lane];

        float mx = fmaxf(v0, v1);
#pragma unroll
        for (int o = 16; o; o >>= 1) mx = fmaxf(mx, __shfl_xor_sync(0xffffffffu, mx, o));
        float p0 = expf(v0 - mx), p1 = expf(v1 - mx);
        float s = p0 + p1;
#pragma unroll
        for (int o = 16; o; o >>= 1) s += __shfl_xor_sync(0xffffffffu, s, o);
        float inv = 1.0f / s;
        atomicAdd(&psum_sh[lane], p0 * inv);
        atomicAdd(&psum_sh[lane + 32], p1 * inv);

        float w0 = v0, w1 = v1;
        float topv[TOPK]; int topi[TOPK];
#pragma unroll
        for (int k = 0; k < TOPK; ++k) {
            float bv; int bi;
            if (w0 >= w1) { bv = w0; bi = lane; } else { bv = w1; bi = lane + 32; }
#pragma unroll
            for (int o = 16; o; o >>= 1) {
                float ov = __shfl_xor_sync(0xffffffffu, bv, o);
                int   oi = __shfl_xor_sync(0xffffffffu, bi, o);
                if (ov > bv || (ov == bv && oi < bi)) { bv = ov; bi = oi; }
            }
            topv[k] = bv; topi[k] = bi;
            if (bi == lane) w0 = NEG_INF;
            if (bi == lane + 32) w1 = NEG_INF;
        }
        float es[TOPK], ss = 0.0f;
#pragma unroll
        for (int k = 0; k < TOPK; ++k) { es[k] = expf(topv[k] - topv[0]); ss += es[k]; }
        float invs = 1.0f / ss;
        float r0 = 0.0f, r1 = 0.0f;
#pragma unroll
        for (int k = 0; k < TOPK; ++k) {
            float w = es[k] * invs;
            if (topi[k] == lane) r0 = w;
            if (topi[k] == lane + 32) r1 = w;
        }
        const int tg = bm + t;
        out_rw[(size_t)tg * NEXP + lane]      = r0;
        out_rw[(size_t)tg * NEXP + 32 + lane] = r1;

        if (lane == 0) {
#pragma unroll
            for (int k = 0; k < TOPK; ++k) {
                if (write_idx) out_idx[(size_t)tg * TOPK + k] = (float)topi[k];
                atomicAdd(&cnt_sh[topi[k]], 1);
            }
        }
    }

    __syncthreads();
    if (tid < NEXP) {
        atomicAdd(&g_probsum[tid], psum_sh[tid]);
        atomicAdd(&g_cnt[tid], cnt_sh[tid]);
    }
}

// ---------------- loss ----------------
__global__ void k_loss(float* __restrict__ out_loss) {
    __shared__ float sh[NEXP];
    int e = threadIdx.x;
    float invN = 1.0f / (float)N_TOK;
    sh[e] = ((float)g_cnt[e] * invN) * (g_probsum[e] * invN);
    __syncthreads();
    if (e < 32) sh[e] += sh[e + 32];
    __syncthreads();
    if (e == 0) {
        float acc = 0.0f;
        for (int i = 0; i < 32; ++i) acc += sh[i];
        *out_loss = (float)NEXP * acc;
    }
}

// ---------------- host launch ----------------
extern "C" void kernel_launch(void* const* d_in, const int* in_sizes, int n_in,
                              void* d_out, int out_size) {
    const float* x  = (const float*)d_in[0];
    const float* W1 = (const float*)d_in[1];
    const float* b1 = (const float*)d_in[2];
    const float* W2 = (const float*)d_in[3];
    const float* b2 = (const float*)d_in[4];

    float* out = (float*)d_out;
    float* out_rw = out;
    float* out_idx = nullptr;
    float* out_loss = nullptr;
    const long rw_elems = (long)N_TOK * NEXP;
    const long idx_elems = (long)N_TOK * TOPK;
    int has_idx = 0;
    if ((long)out_size >= rw_elems + idx_elems) { out_idx = out + rw_elems; has_idx = 1; }
    if ((long)out_size >= rw_elems + idx_elems + 1) out_loss = out + rw_elems + idx_elems;

    constexpr int SM1 = 3 * (2 * 128 * 64 + 2 * 128 * 64);  // 98304
    constexpr int SM2 = 3 * (2 * 64 * 64 + 2 * 64 * 64);    // 49152
    cudaFuncSetAttribute(k_mma1,   cudaFuncAttributeMaxDynamicSharedMemorySize, SM1);
    cudaFuncSetAttribute(k_gemm2r, cudaFuncAttributeMaxDynamicSharedMemorySize, SM2);

    k_prep<<<8320, 256>>>(x, W1, W2);

    k_mma1<<<dim3(16, 128), 256, SM1>>>(b1);

    k_gemm2r<<<dim3(256), 256, SM2>>>(b2, out_rw, out_idx, has_idx);

    if (out_loss) k_loss<<<1, 64>>>(out_loss);
}